// round 2
// baseline (speedup 1.0000x reference)
#include <cuda_runtime.h>
#include <math.h>

#define NMAX 10000
#define EMAX 160000

// ---------------- scratch (static device globals; no allocation) ----------------
__device__ float g_hA[NMAX * 64];
__device__ float g_hB[NMAX * 64];
__device__ float g_h256[NMAX * 256];
__device__ float g_msg[EMAX * 64];          // per-edge messages, dst-sorted slots
__device__ float g_basisE[EMAX * 8];        // basis in edge order
__device__ int   g_cellE[EMAX];
__device__ int   g_srcC[EMAX];              // src node, cell-sorted order
__device__ int   g_slotC[EMAX];             // dst-sorted slot, cell-sorted order
__device__ float g_basisC[EMAX * 8];        // basis, cell-sorted order
__device__ int   g_cellCnt[64];
__device__ int   g_cellStart[65];
__device__ int   g_cellPtr[64];
__device__ int   g_deg[NMAX];
__device__ int   g_dstStart[NMAX + 1];
__device__ int   g_dstPtr[NMAX];
__device__ int   g_chunkCell[4608];
__device__ int   g_chunkBeg[4608];
__device__ int   g_numChunks;

// ---------------- init: zero counters ----------------
__global__ void k_init(int N) {
    int i = blockIdx.x * blockDim.x + threadIdx.x;
    if (i < 64) g_cellCnt[i] = 0;
    if (i < N)  g_deg[i] = 0;
}

// ---------------- per-edge: basis, cell, histograms ----------------
__global__ void k_prep(const int* __restrict__ ei, const float* __restrict__ ps, int E) {
    int e = blockIdx.x * blockDim.x + threadIdx.x;
    if (e >= E) return;
    int dst = ei[E + e];
    float fr[3];
    int lo[3];
#pragma unroll
    for (int d = 0; d < 3; d++) {
        float pos = ps[e * 3 + d] * 4.0f;   // (K-1) = 4
        float l = floorf(pos);
        l = fminf(fmaxf(l, 0.0f), 3.0f);    // clip to [0, K-2]
        lo[d] = (int)l;
        fr[d] = pos - l;
    }
    int cell = lo[0] * 16 + lo[1] * 4 + lo[2];
    g_cellE[e] = cell;
#pragma unroll
    for (int b = 0; b < 8; b++) {
        float w = 1.0f;
#pragma unroll
        for (int d = 0; d < 3; d++) w *= ((b >> d) & 1) ? fr[d] : (1.0f - fr[d]);
        g_basisE[e * 8 + b] = w;
    }
    atomicAdd(&g_cellCnt[cell], 1);
    atomicAdd(&g_deg[dst], 1);
}

// ---------------- single-block scans + chunk list ----------------
__global__ void k_scan(int N, int E) {
    __shared__ int sh[1024];
    __shared__ int carry;
    int tid = threadIdx.x;
    if (tid == 0) {
        int s = 0;
        for (int c = 0; c < 64; c++) { g_cellStart[c] = s; g_cellPtr[c] = s; s += g_cellCnt[c]; }
        g_cellStart[64] = s;
        int t = 0;
        for (int c = 0; c < 64; c++)
            for (int b = g_cellStart[c]; b < g_cellStart[c + 1]; b += 64) {
                g_chunkCell[t] = c; g_chunkBeg[t] = b; t++;
            }
        g_numChunks = t;
        carry = 0;
        g_dstStart[0] = 0;
    }
    __syncthreads();
    for (int base = 0; base < N; base += 1024) {
        int v = (base + tid < N) ? g_deg[base + tid] : 0;
        sh[tid] = v;
        __syncthreads();
        for (int off = 1; off < 1024; off <<= 1) {
            int t2 = 0;
            if (tid >= off) t2 = sh[tid - off];
            __syncthreads();
            if (tid >= off) sh[tid] += t2;
            __syncthreads();
        }
        if (base + tid < N) g_dstStart[base + tid + 1] = carry + sh[tid];
        __syncthreads();
        if (tid == 0) carry += sh[1023];
        __syncthreads();
    }
    for (int i = tid; i < N; i += 1024) g_dstPtr[i] = g_dstStart[i];
}

// ---------------- scatter into cell-sorted + dst-sorted orders ----------------
__global__ void k_scatter(const int* __restrict__ ei, int E) {
    int e = blockIdx.x * blockDim.x + threadIdx.x;
    if (e >= E) return;
    int src = ei[e], dst = ei[E + e];
    int c = g_cellE[e];
    int p = atomicAdd(&g_cellPtr[c], 1);
    int q = atomicAdd(&g_dstPtr[dst], 1);
    g_srcC[p] = src;
    g_slotC[p] = q;
#pragma unroll
    for (int b = 0; b < 8; b++) g_basisC[p * 8 + b] = g_basisE[e * 8 + b];
}

// ---------------- spline conv GEMM: 64-edge tile x W[corner] ----------------
template <int CI, int CO>
__global__ void __launch_bounds__(256) k_conv_gemm(const float* __restrict__ xin,
                                                   const float* __restrict__ W) {
    constexpr int TN = CO / 16;                 // cols per thread (4 for 64, 2 for 32)
    __shared__ float Xs[64][CI + 1];
    __align__(16) __shared__ float Ws[CI * CO];
    __shared__ float Bs[64][8];
    __shared__ int   Sslot[64];

    int bi = blockIdx.x;
    if (bi >= g_numChunks) return;
    int cell = g_chunkCell[bi];
    int beg  = g_chunkBeg[bi];
    int end  = min(beg + 64, g_cellStart[cell + 1]);
    int R = end - beg;
    int tid = threadIdx.x;

    {   // gather: 4 threads per row
        int r = tid >> 2, g = tid & 3;
        bool valid = r < R;
        int src = valid ? g_srcC[beg + r] : 0;
        if (g == 0) {
            Sslot[r] = valid ? g_slotC[beg + r] : -1;
#pragma unroll
            for (int b = 0; b < 8; b++) Bs[r][b] = valid ? g_basisC[(beg + r) * 8 + b] : 0.0f;
        }
        for (int k = g; k < CI; k += 4) Xs[r][k] = valid ? xin[src * CI + k] : 0.0f;
    }

    int c0 = (tid & 15) * TN;
    int r0 = (tid >> 4) * 4;
    float acc[4][TN];
#pragma unroll
    for (int r = 0; r < 4; r++)
#pragma unroll
        for (int c = 0; c < TN; c++) acc[r][c] = 0.0f;

    int ix = cell >> 4, iy = (cell >> 2) & 3, iz = cell & 3;
#pragma unroll
    for (int b = 0; b < 8; b++) {
        int kb = (ix + (b & 1)) * 25 + (iy + ((b >> 1) & 1)) * 5 + (iz + ((b >> 2) & 1));
        __syncthreads();
        const float4* wsrc = (const float4*)(W + (size_t)kb * CI * CO);
        for (int i = tid; i < CI * CO / 4; i += 256) ((float4*)Ws)[i] = wsrc[i];
        __syncthreads();

        float p[4][TN];
#pragma unroll
        for (int r = 0; r < 4; r++)
#pragma unroll
            for (int c = 0; c < TN; c++) p[r][c] = 0.0f;

#pragma unroll 4
        for (int k = 0; k < CI; k++) {
            float a[4];
#pragma unroll
            for (int r = 0; r < 4; r++) a[r] = Xs[r0 + r][k];
            float wv[TN];
#pragma unroll
            for (int c = 0; c < TN; c++) wv[c] = Ws[k * CO + c0 + c];
#pragma unroll
            for (int r = 0; r < 4; r++)
#pragma unroll
                for (int c = 0; c < TN; c++) p[r][c] += a[r] * wv[c];
        }
#pragma unroll
        for (int r = 0; r < 4; r++) {
            float bs = Bs[r0 + r][b];
#pragma unroll
            for (int c = 0; c < TN; c++) acc[r][c] += bs * p[r][c];
        }
    }

#pragma unroll
    for (int r = 0; r < 4; r++) {
        int rr = r0 + r;
        if (rr < R) {
            float* dstp = &g_msg[(size_t)Sslot[rr] * CO + c0];
#pragma unroll
            for (int c = 0; c < TN; c++) dstp[c] = acc[r][c];
        }
    }
}

// ---------------- segmented mean + root + bias + ELU ----------------
template <int CI, int CO>
__global__ void k_conv_reduce(const float* __restrict__ xin, const float* __restrict__ root,
                              const float* __restrict__ bias, float* __restrict__ xout, int N) {
    constexpr int NPB = 128 / CO;
    int n = blockIdx.x * NPB + threadIdx.x / CO;
    int j = threadIdx.x % CO;
    if (n >= N) return;
    int s0 = g_dstStart[n], s1 = g_dstStart[n + 1];
    float s = 0.0f;
    for (int r = s0; r < s1; r++) s += g_msg[(size_t)r * CO + j];
    float d = (float)max(g_deg[n], 1);
    float rt = 0.0f;
#pragma unroll 8
    for (int ci = 0; ci < CI; ci++) rt += xin[n * CI + ci] * root[ci * CO + j];
    float v = s / d + rt + bias[j];
    xout[(size_t)n * CO + j] = v > 0.0f ? v : expm1f(v);
}

// ---------------- dense FC GEMM (64x64 tiles) ----------------
template <int KD, bool DOELU>
__global__ void __launch_bounds__(256) k_fc(const float* __restrict__ A, const float* __restrict__ B,
                                            const float* __restrict__ bias, float* __restrict__ C,
                                            int M, int NC) {
    __shared__ float As[64 * 65];
    __shared__ float Bs[64 * 64];
    int rb = blockIdx.x * 64, cb = blockIdx.y * 64;
    int tid = threadIdx.x;
    int c0 = (tid & 15) * 4, r0 = (tid >> 4) * 4;
    float acc[4][4];
#pragma unroll
    for (int r = 0; r < 4; r++)
#pragma unroll
        for (int c = 0; c < 4; c++) acc[r][c] = 0.0f;

    for (int kc = 0; kc < KD; kc += 64) {
        __syncthreads();
        for (int i = tid; i < 64 * 64; i += 256) {
            int r = i >> 6, c = i & 63;
            int gr = rb + r;
            As[r * 65 + c] = (gr < M) ? A[(size_t)gr * KD + kc + c] : 0.0f;
            Bs[i] = B[(size_t)(kc + r) * NC + cb + c];
        }
        __syncthreads();
#pragma unroll 4
        for (int k = 0; k < 64; k++) {
            float a[4], wv[4];
#pragma unroll
            for (int r = 0; r < 4; r++) a[r] = As[(r0 + r) * 65 + k];
#pragma unroll
            for (int c = 0; c < 4; c++) wv[c] = Bs[k * 64 + c0 + c];
#pragma unroll
            for (int r = 0; r < 4; r++)
#pragma unroll
                for (int c = 0; c < 4; c++) acc[r][c] += a[r] * wv[c];
        }
    }
#pragma unroll
    for (int r = 0; r < 4; r++) {
        int gr = rb + r0 + r;
        if (gr >= M) continue;
#pragma unroll
        for (int c = 0; c < 4; c++) {
            float v = acc[r][c] + bias[cb + c0 + c];
            if (DOELU) v = v > 0.0f ? v : expm1f(v);
            C[(size_t)gr * NC + cb + c0 + c] = v;
        }
    }
}

// ---------------- log_softmax over 1024 cols, in place ----------------
__global__ void k_lsm(float* __restrict__ out) {
    __shared__ float red[256];
    int n = blockIdx.x;
    float* row = out + (size_t)n * 1024;
    int tid = threadIdx.x;
    float v[4];
    float m = -INFINITY;
#pragma unroll
    for (int i = 0; i < 4; i++) { v[i] = row[tid + 256 * i]; m = fmaxf(m, v[i]); }
    red[tid] = m;
    __syncthreads();
    for (int off = 128; off; off >>= 1) {
        if (tid < off) red[tid] = fmaxf(red[tid], red[tid + off]);
        __syncthreads();
    }
    m = red[0];
    __syncthreads();
    float s = 0.0f;
#pragma unroll
    for (int i = 0; i < 4; i++) s += expf(v[i] - m);
    red[tid] = s;
    __syncthreads();
    for (int off = 128; off; off >>= 1) {
        if (tid < off) red[tid] += red[tid + off];
        __syncthreads();
    }
    float l = m + logf(red[0]);
#pragma unroll
    for (int i = 0; i < 4; i++) row[tid + 256 * i] = v[i] - l;
}

// ---------------- launcher ----------------
extern "C" void kernel_launch(void* const* d_in, const int* in_sizes, int n_in,
                              void* d_out, int out_size) {
    const float* x      = (const float*)d_in[0];
    const int*   ei     = (const int*)d_in[1];
    const float* pseudo = (const float*)d_in[2];
    const float *w[6], *root[6], *bias[6];
    for (int i = 0; i < 6; i++) {
        w[i]    = (const float*)d_in[3 + 3 * i];
        root[i] = (const float*)d_in[4 + 3 * i];
        bias[i] = (const float*)d_in[5 + 3 * i];
    }
    const float* fc1w = (const float*)d_in[21];
    const float* fc1b = (const float*)d_in[22];
    const float* fc2w = (const float*)d_in[23];
    const float* fc2b = (const float*)d_in[24];
    float* out = (float*)d_out;

    int N = in_sizes[0];          // x is [N,1]
    int E = in_sizes[1] / 2;

    int eg = (E + 255) / 256;
    int ng = (N + 255) / 256;
    int nchunks = (E + 63) / 64 + 64;

    float* hA = nullptr; cudaGetSymbolAddress((void**)&hA, g_hA);
    float* hB = nullptr; cudaGetSymbolAddress((void**)&hB, g_hB);
    float* h256 = nullptr; cudaGetSymbolAddress((void**)&h256, g_h256);

    k_init<<<ng, 256>>>(N);
    k_prep<<<eg, 256>>>(ei, pseudo, E);
    k_scan<<<1, 1024>>>(N, E);
    k_scatter<<<eg, 256>>>(ei, E);

    // layer 1: 1 -> 32
    k_conv_gemm<1, 32><<<nchunks, 256>>>(x, w[0]);
    k_conv_reduce<1, 32><<<(N + 3) / 4, 128>>>(x, root[0], bias[0], hA, N);
    // layer 2: 32 -> 64
    k_conv_gemm<32, 64><<<nchunks, 256>>>(hA, w[1]);
    k_conv_reduce<32, 64><<<(N + 1) / 2, 128>>>(hA, root[1], bias[1], hB, N);
    // layer 3
    k_conv_gemm<64, 64><<<nchunks, 256>>>(hB, w[2]);
    k_conv_reduce<64, 64><<<(N + 1) / 2, 128>>>(hB, root[2], bias[2], hA, N);
    // layer 4
    k_conv_gemm<64, 64><<<nchunks, 256>>>(hA, w[3]);
    k_conv_reduce<64, 64><<<(N + 1) / 2, 128>>>(hA, root[3], bias[3], hB, N);
    // layer 5
    k_conv_gemm<64, 64><<<nchunks, 256>>>(hB, w[4]);
    k_conv_reduce<64, 64><<<(N + 1) / 2, 128>>>(hB, root[4], bias[4], hA, N);
    // layer 6
    k_conv_gemm<64, 64><<<nchunks, 256>>>(hA, w[5]);
    k_conv_reduce<64, 64><<<(N + 1) / 2, 128>>>(hA, root[5], bias[5], hB, N);

    // fc1: [N,64] @ [64,256] + ELU
    k_fc<64, true><<<dim3((N + 63) / 64, 4), 256>>>(hB, fc1w, fc1b, h256, N, 256);
    // fc2: [N,256] @ [256,1024]
    k_fc<256, false><<<dim3((N + 63) / 64, 16), 256>>>(h256, fc2w, fc2b, out, N, 1024);
    // log_softmax in place
    k_lsm<<<N, 256>>>(out);
}

// round 5
// speedup vs baseline: 2.6194x; 2.6194x over previous
#include <cuda_runtime.h>
#include <math.h>
#include <stdint.h>

#define NMAX 10000
#define EMAX 160000
#define NCHUNKMAX 4608

// ---------------- scratch (static device globals; no allocation) ----------------
__device__ float g_hA[NMAX * 64];
__device__ float g_hB[NMAX * 64];
__device__ float g_h256[NMAX * 256];
__device__ float g_msg[EMAX * 64];          // per-edge messages, dst-sorted slots
__device__ float g_basisE[EMAX * 8];        // basis in edge order
__device__ int   g_cellE[EMAX];
__device__ int   g_rankC[EMAX];
__device__ int   g_rankD[EMAX];
__device__ int   g_slotE[EMAX];             // dst-sorted slot, edge order
__device__ int   g_srcC[EMAX];              // src node, cell-sorted order
__device__ int   g_slotC[EMAX];             // dst-sorted slot, cell-sorted order
__device__ float g_basisC[EMAX * 8];        // basis, cell-sorted order
__device__ int   g_cellCnt[64];
__device__ int   g_cellStart[65];
__device__ int   g_deg[NMAX];
__device__ int   g_dstStart[NMAX + 1];
__device__ int   g_chunkCell[NCHUNKMAX];
__device__ int   g_chunkBeg[NCHUNKMAX];
__device__ int   g_numChunks;

// ---------------- m16n8k8 tf32 mma.sync (sm_80+, valid on plain sm_100) ----------------
__device__ __forceinline__ void mma1688(float* d, uint32_t a0, uint32_t a1, uint32_t a2, uint32_t a3,
                                        uint32_t b0, uint32_t b1) {
    asm volatile(
        "mma.sync.aligned.m16n8k8.row.col.f32.tf32.tf32.f32 "
        "{%0,%1,%2,%3}, {%4,%5,%6,%7}, {%8,%9}, {%0,%1,%2,%3};"
        : "+f"(d[0]), "+f"(d[1]), "+f"(d[2]), "+f"(d[3])
        : "r"(a0), "r"(a1), "r"(a2), "r"(a3), "r"(b0), "r"(b1));
}

// ---------------- init ----------------
__global__ void k_init(int N) {
    int i = blockIdx.x * blockDim.x + threadIdx.x;
    if (i < 64) g_cellCnt[i] = 0;
    if (i < N)  g_deg[i] = 0;
}

// ---------------- per-edge: basis, cell, ranks ----------------
__global__ void k_prep(const int* __restrict__ ei, const float* __restrict__ ps, int E) {
    int e = blockIdx.x * blockDim.x + threadIdx.x;
    if (e >= E) return;
    int dst = ei[E + e];
    float fr[3];
    int lo[3];
#pragma unroll
    for (int d = 0; d < 3; d++) {
        float pos = ps[e * 3 + d] * 4.0f;   // (K-1) = 4
        float l = floorf(pos);
        l = fminf(fmaxf(l, 0.0f), 3.0f);    // clip to [0, K-2]
        lo[d] = (int)l;
        fr[d] = pos - l;
    }
    int cell = lo[0] * 16 + lo[1] * 4 + lo[2];
    g_cellE[e] = cell;
#pragma unroll
    for (int b = 0; b < 8; b++) {
        float w = 1.0f;
#pragma unroll
        for (int d = 0; d < 3; d++) w *= ((b >> d) & 1) ? fr[d] : (1.0f - fr[d]);
        g_basisE[e * 8 + b] = w;
    }
    g_rankC[e] = atomicAdd(&g_cellCnt[cell], 1);
    g_rankD[e] = atomicAdd(&g_deg[dst], 1);
}

// ---------------- scans + chunk list (128-row chunks) ----------------
__global__ void k_scan(int N, int E) {
    __shared__ int sh[1024];
    __shared__ int chOff[64];
    __shared__ int carry;
    int tid = threadIdx.x;
    if (tid == 0) {
        int s = 0;
        for (int c = 0; c < 64; c++) { g_cellStart[c] = s; s += g_cellCnt[c]; }
        g_cellStart[64] = s;
        int t = 0;
        for (int c = 0; c < 64; c++) { chOff[c] = t; t += (g_cellCnt[c] + 127) / 128; }
        g_numChunks = t;
        carry = 0;
        g_dstStart[0] = 0;
    }
    __syncthreads();
    if (tid < 64) {
        int t = chOff[tid];
        for (int b = g_cellStart[tid]; b < g_cellStart[tid + 1]; b += 128) {
            g_chunkCell[t] = tid; g_chunkBeg[t] = b; t++;
        }
    }
    for (int base = 0; base < N; base += 1024) {
        int v = (base + tid < N) ? g_deg[base + tid] : 0;
        sh[tid] = v;
        __syncthreads();
        for (int off = 1; off < 1024; off <<= 1) {
            int t2 = 0;
            if (tid >= off) t2 = sh[tid - off];
            __syncthreads();
            if (tid >= off) sh[tid] += t2;
            __syncthreads();
        }
        if (base + tid < N) g_dstStart[base + tid + 1] = carry + sh[tid];
        __syncthreads();
        if (tid == 0) carry += sh[1023];
        __syncthreads();
    }
}

// ---------------- scatter (no atomics: ranks precomputed) ----------------
__global__ void k_scatter(const int* __restrict__ ei, int E) {
    int e = blockIdx.x * blockDim.x + threadIdx.x;
    if (e >= E) return;
    int src = ei[e], dst = ei[E + e];
    int p = g_cellStart[g_cellE[e]] + g_rankC[e];
    int q = g_dstStart[dst] + g_rankD[e];
    g_srcC[p] = src;
    g_slotC[p] = q;
    g_slotE[e] = q;
#pragma unroll
    for (int b = 0; b < 8; b++) g_basisC[p * 8 + b] = g_basisE[e * 8 + b];
}

// ---------------- tf32 mma spline-conv: 128-edge chunk x CO=64 ----------------
// 8 warps as 4(m) x 2(n); warp tile 32x32 = 2 m-atoms x 4 n-atoms of m16n8k8.
// A = basis-scaled X (scale applied in registers), B = W[corner] staged per corner.
template <int CI>
__global__ void __launch_bounds__(256) k_conv_mma(const float* __restrict__ xin,
                                                  const float* __restrict__ W) {
    constexpr int XPAD = CI + 4;           // bank = (4*row + k) % 32 -> conflict-free A frags
    constexpr int WPAD = 72;               // bank = (8*k + c) % 32 -> conflict-free B frags
    constexpr int CH = CI / 2;             // floats per thread of one X row (2 thr/row)
    extern __shared__ float sm[];
    int*   slots = (int*)sm;               // 128
    float* bsm   = sm + 128;               // 128 x 8 basis
    float* Xs    = bsm + 1024;             // 128 x XPAD
    float* Ws    = Xs + 128 * XPAD;        // CI x WPAD

    int bi = blockIdx.x;
    if (bi >= g_numChunks) return;
    int cell = g_chunkCell[bi];
    int beg  = g_chunkBeg[bi];
    int R = min(beg + 128, g_cellStart[cell + 1]) - beg;

    int tid = threadIdx.x, wid = tid >> 5, lid = tid & 31;
    {   // stage slots, basis, X (2 threads per row)
        int r = tid >> 1, half = tid & 1;
        if (half == 0) {
            slots[r] = (r < R) ? g_slotC[beg + r] : -1;
#pragma unroll
            for (int b = 0; b < 8; b++)
                bsm[r * 8 + b] = (r < R) ? g_basisC[(beg + r) * 8 + b] : 0.0f;
        }
        int src = (r < R) ? g_srcC[beg + r] : 0;
        const float4* xp = (const float4*)(xin + (size_t)src * CI + half * CH);
#pragma unroll
        for (int i = 0; i < CH / 4; i++) {
            float4 v = (r < R) ? xp[i] : make_float4(0.f, 0.f, 0.f, 0.f);
            *(float4*)&Xs[r * XPAD + half * CH + i * 4] = v;
        }
    }

    int wm = wid >> 1, wn = wid & 1;       // warp tile: rows wm*32, cols wn*32
    int g = lid >> 2, q = lid & 3;
    float acc[2][4][4];
#pragma unroll
    for (int m = 0; m < 2; m++)
#pragma unroll
        for (int n = 0; n < 4; n++)
#pragma unroll
            for (int i = 0; i < 4; i++) acc[m][n][i] = 0.0f;

    int ix = cell >> 4, iy = (cell >> 2) & 3, iz = cell & 3;

    for (int b = 0; b < 8; b++) {
        int kb = (ix + (b & 1)) * 25 + (iy + ((b >> 1) & 1)) * 5 + (iz + ((b >> 2) & 1));
        __syncthreads();                   // all warps done reading previous Ws
        {
            const float4* wp = (const float4*)(W + (size_t)kb * CI * 64);
            for (int i = tid; i < CI * 16; i += 256) {
                int row = i >> 4, c4 = i & 15;
                *(float4*)&Ws[row * WPAD + c4 * 4] = wp[i];
            }
        }
        __syncthreads();

        float s0[2], s1[2];
#pragma unroll
        for (int m = 0; m < 2; m++) {
            int rr = wm * 32 + m * 16 + g;
            s0[m] = bsm[rr * 8 + b];
            s1[m] = bsm[(rr + 8) * 8 + b];
        }

#pragma unroll
        for (int ks = 0; ks < CI / 8; ks++) {
            int k0 = ks * 8;
            uint32_t B0[4], B1[4];
#pragma unroll
            for (int n = 0; n < 4; n++) {
                int c = wn * 32 + n * 8 + g;
                B0[n] = __float_as_uint(Ws[(k0 + q) * WPAD + c]);
                B1[n] = __float_as_uint(Ws[(k0 + q + 4) * WPAD + c]);
            }
#pragma unroll
            for (int m = 0; m < 2; m++) {
                int rr = wm * 32 + m * 16 + g;
                uint32_t a0 = __float_as_uint(Xs[rr * XPAD + k0 + q] * s0[m]);
                uint32_t a1 = __float_as_uint(Xs[(rr + 8) * XPAD + k0 + q] * s1[m]);
                uint32_t a2 = __float_as_uint(Xs[rr * XPAD + k0 + q + 4] * s0[m]);
                uint32_t a3 = __float_as_uint(Xs[(rr + 8) * XPAD + k0 + q + 4] * s1[m]);
#pragma unroll
                for (int n = 0; n < 4; n++)
                    mma1688(acc[m][n], a0, a1, a2, a3, B0[n], B1[n]);
            }
        }
    }

    // store: d0/d1 at (row g, col 2q/2q+1), d2/d3 at (row g+8)
#pragma unroll
    for (int m = 0; m < 2; m++)
#pragma unroll
        for (int h = 0; h < 2; h++) {
            int row = wm * 32 + m * 16 + g + h * 8;
            int slot = slots[row];
            if (slot >= 0) {
                float* base = g_msg + (size_t)slot * 64 + wn * 32;
#pragma unroll
                for (int n = 0; n < 4; n++)
                    *(float2*)&base[n * 8 + q * 2] =
                        make_float2(acc[m][n][h * 2], acc[m][n][h * 2 + 1]);
            }
        }
}

// ---------------- layer 1 (CI=1, CO=32): warp-per-edge ----------------
__global__ void k_conv1(const float* __restrict__ x, const int* __restrict__ ei,
                        const float* __restrict__ w1, int E) {
    int e = blockIdx.x * 8 + (threadIdx.x >> 5);
    if (e >= E) return;
    int c = threadIdx.x & 31;
    int cell = g_cellE[e];
    int ix = cell >> 4, iy = (cell >> 2) & 3, iz = cell & 3;
    float acc = 0.0f;
#pragma unroll
    for (int b = 0; b < 8; b++) {
        int kb = (ix + (b & 1)) * 25 + (iy + ((b >> 1) & 1)) * 5 + (iz + ((b >> 2) & 1));
        acc += g_basisE[e * 8 + b] * w1[kb * 32 + c];
    }
    g_msg[(size_t)g_slotE[e] * 32 + c] = x[ei[e]] * acc;
}

// ---------------- segmented mean + root + bias + ELU ----------------
template <int CI, int CO>
__global__ void k_conv_reduce(const float* __restrict__ xin, const float* __restrict__ root,
                              const float* __restrict__ bias, float* __restrict__ xout, int N) {
    constexpr int NPB = 128 / CO;
    int n = blockIdx.x * NPB + threadIdx.x / CO;
    int j = threadIdx.x % CO;
    if (n >= N) return;
    int s0 = g_dstStart[n], s1 = g_dstStart[n + 1];
    float s = 0.0f;
    for (int r = s0; r < s1; r++) s += g_msg[(size_t)r * CO + j];
    float d = (float)max(g_deg[n], 1);
    float rt = 0.0f;
#pragma unroll 8
    for (int ci = 0; ci < CI; ci++) rt += xin[n * CI + ci] * root[ci * CO + j];
    float v = s / d + rt + bias[j];
    xout[(size_t)n * CO + j] = v > 0.0f ? v : expm1f(v);
}

// ---------------- FC GEMM via tf32 mma: block 64x128, warp 32x32 ----------------
template <int KD, bool DOELU>
__global__ void __launch_bounds__(256) k_fc_mma(const float* __restrict__ A,
                                                const float* __restrict__ B,
                                                const float* __restrict__ bias,
                                                float* __restrict__ C, int M, int NC) {
    constexpr int APAD = 68, BPAD = 136;
    extern __shared__ float sm[];
    float* As = sm;                         // 64 x APAD
    float* Bs = sm + 64 * APAD;             // 64 x BPAD
    int rb = blockIdx.x * 64, cb = blockIdx.y * 128;
    int tid = threadIdx.x, wid = tid >> 5, lid = tid & 31;
    int wm = wid >> 2, wn = wid & 3;        // 2 x 4 warps
    int g = lid >> 2, q = lid & 3;

    float acc[2][4][4];
#pragma unroll
    for (int m = 0; m < 2; m++)
#pragma unroll
        for (int n = 0; n < 4; n++)
#pragma unroll
            for (int i = 0; i < 4; i++) acc[m][n][i] = 0.0f;

    for (int kc = 0; kc < KD; kc += 64) {
        __syncthreads();
        for (int i = tid; i < 1024; i += 256) {     // A tile 64x64
            int row = i >> 4, c4 = i & 15;
            int gr = rb + row;
            float4 v = (gr < M) ? *(const float4*)&A[(size_t)gr * KD + kc + c4 * 4]
                                : make_float4(0.f, 0.f, 0.f, 0.f);
            *(float4*)&As[row * APAD + c4 * 4] = v;
        }
        for (int i = tid; i < 2048; i += 256) {     // B tile 64x128
            int row = i >> 5, c4 = i & 31;
            *(float4*)&Bs[row * BPAD + c4 * 4] =
                *(const float4*)&B[(size_t)(kc + row) * NC + cb + c4 * 4];
        }
        __syncthreads();
#pragma unroll
        for (int ks = 0; ks < 8; ks++) {
            int k0 = ks * 8;
            uint32_t B0[4], B1[4];
#pragma unroll
            for (int n = 0; n < 4; n++) {
                int c = wn * 32 + n * 8 + g;
                B0[n] = __float_as_uint(Bs[(k0 + q) * BPAD + c]);
                B1[n] = __float_as_uint(Bs[(k0 + q + 4) * BPAD + c]);
            }
#pragma unroll
            for (int m = 0; m < 2; m++) {
                int rr = wm * 32 + m * 16 + g;
                uint32_t a0 = __float_as_uint(As[rr * APAD + k0 + q]);
                uint32_t a1 = __float_as_uint(As[(rr + 8) * APAD + k0 + q]);
                uint32_t a2 = __float_as_uint(As[rr * APAD + k0 + q + 4]);
                uint32_t a3 = __float_as_uint(As[(rr + 8) * APAD + k0 + q + 4]);
#pragma unroll
                for (int n = 0; n < 4; n++)
                    mma1688(acc[m][n], a0, a1, a2, a3, B0[n], B1[n]);
            }
        }
    }

#pragma unroll
    for (int m = 0; m < 2; m++)
#pragma unroll
        for (int h = 0; h < 2; h++) {
            int gr = rb + wm * 32 + m * 16 + g + h * 8;
            if (gr >= M) continue;
#pragma unroll
            for (int n = 0; n < 4; n++) {
                int col = cb + wn * 32 + n * 8 + q * 2;
                float v0 = acc[m][n][h * 2] + bias[col];
                float v1 = acc[m][n][h * 2 + 1] + bias[col + 1];
                if (DOELU) {
                    v0 = v0 > 0.0f ? v0 : expm1f(v0);
                    v1 = v1 > 0.0f ? v1 : expm1f(v1);
                }
                *(float2*)&C[(size_t)gr * NC + col] = make_float2(v0, v1);
            }
        }
}

// ---------------- log_softmax over 1024 cols, in place ----------------
__global__ void k_lsm(float* __restrict__ out) {
    __shared__ float red[256];
    int n = blockIdx.x;
    float* row = out + (size_t)n * 1024;
    int tid = threadIdx.x;
    float v[4];
    float m = -INFINITY;
#pragma unroll
    for (int i = 0; i < 4; i++) { v[i] = row[tid + 256 * i]; m = fmaxf(m, v[i]); }
    red[tid] = m;
    __syncthreads();
    for (int off = 128; off; off >>= 1) {
        if (tid < off) red[tid] = fmaxf(red[tid], red[tid + off]);
        __syncthreads();
    }
    m = red[0];
    __syncthreads();
    float s = 0.0f;
#pragma unroll
    for (int i = 0; i < 4; i++) s += expf(v[i] - m);
    red[tid] = s;
    __syncthreads();
    for (int off = 128; off; off >>= 1) {
        if (tid < off) red[tid] += red[tid + off];
        __syncthreads();
    }
    float l = m + logf(red[0]);
#pragma unroll
    for (int i = 0; i < 4; i++) row[tid + 256 * i] = v[i] - l;
}

// ---------------- launcher ----------------
extern "C" void kernel_launch(void* const* d_in, const int* in_sizes, int n_in,
                              void* d_out, int out_size) {
    const float* x      = (const float*)d_in[0];
    const int*   ei     = (const int*)d_in[1];
    const float* pseudo = (const float*)d_in[2];
    const float *w[6], *root[6], *bias[6];
    for (int i = 0; i < 6; i++) {
        w[i]    = (const float*)d_in[3 + 3 * i];
        root[i] = (const float*)d_in[4 + 3 * i];
        bias[i] = (const float*)d_in[5 + 3 * i];
    }
    const float* fc1w = (const float*)d_in[21];
    const float* fc1b = (const float*)d_in[22];
    const float* fc2w = (const float*)d_in[23];
    const float* fc2b = (const float*)d_in[24];
    float* out = (float*)d_out;

    int N = in_sizes[0];
    int E = in_sizes[1] / 2;

    int eg = (E + 255) / 256;
    int ng = (N + 255) / 256;
    int nchunks = (E + 127) / 128 + 64;

    float* hA = nullptr; cudaGetSymbolAddress((void**)&hA, g_hA);
    float* hB = nullptr; cudaGetSymbolAddress((void**)&hB, g_hB);
    float* h256 = nullptr; cudaGetSymbolAddress((void**)&h256, g_h256);

    // dynamic smem sizes
    constexpr int CSM64 = (128 + 1024 + 128 * 68 + 64 * 72) * 4;   // 57856
    constexpr int CSM32 = (128 + 1024 + 128 * 36 + 32 * 72) * 4;   // 32256
    constexpr int FSM   = (64 * 68 + 64 * 136) * 4;                // 52224
    cudaFuncSetAttribute(k_conv_mma<64>, cudaFuncAttributeMaxDynamicSharedMemorySize, CSM64);
    cudaFuncSetAttribute(k_conv_mma<32>, cudaFuncAttributeMaxDynamicSharedMemorySize, CSM32);
    cudaFuncSetAttribute(k_fc_mma<64, true>, cudaFuncAttributeMaxDynamicSharedMemorySize, FSM);
    cudaFuncSetAttribute(k_fc_mma<256, false>, cudaFuncAttributeMaxDynamicSharedMemorySize, FSM);

    k_init<<<ng, 256>>>(N);
    k_prep<<<eg, 256>>>(ei, pseudo, E);
    k_scan<<<1, 1024>>>(N, E);
    k_scatter<<<eg, 256>>>(ei, E);

    // layer 1: 1 -> 32 (SIMT, warp per edge)
    k_conv1<<<(E + 7) / 8, 256>>>(x, ei, w[0], E);
    k_conv_reduce<1, 32><<<(N + 3) / 4, 128>>>(x, root[0], bias[0], hA, N);
    // layer 2: 32 -> 64 (tf32 mma)
    k_conv_mma<32><<<nchunks, 256, CSM32>>>(hA, w[1]);
    k_conv_reduce<32, 64><<<(N + 1) / 2, 128>>>(hA, root[1], bias[1], hB, N);
    // layers 3-6: 64 -> 64 (tf32 mma)
    k_conv_mma<64><<<nchunks, 256, CSM64>>>(hB, w[2]);
    k_conv_reduce<64, 64><<<(N + 1) / 2, 128>>>(hB, root[2], bias[2], hA, N);
    k_conv_mma<64><<<nchunks, 256, CSM64>>>(hA, w[3]);
    k_conv_reduce<64, 64><<<(N + 1) / 2, 128>>>(hA, root[3], bias[3], hB, N);
    k_conv_mma<64><<<nchunks, 256, CSM64>>>(hB, w[4]);
    k_conv_reduce<64, 64><<<(N + 1) / 2, 128>>>(hB, root[4], bias[4], hA, N);
    k_conv_mma<64><<<nchunks, 256, CSM64>>>(hA, w[5]);
    k_conv_reduce<64, 64><<<(N + 1) / 2, 128>>>(hA, root[5], bias[5], hB, N);

    // fc1: [N,64] @ [64,256] + ELU
    k_fc_mma<64, true><<<dim3((N + 63) / 64, 2), 256, FSM>>>(hB, fc1w, fc1b, h256, N, 256);
    // fc2: [N,256] @ [256,1024]
    k_fc_mma<256, false><<<dim3((N + 63) / 64, 8), 256, FSM>>>(h256, fc2w, fc2b, out, N, 1024);
    // log_softmax in place
    k_lsm<<<N, 256>>>(out);
}

// round 6
// speedup vs baseline: 2.9539x; 1.1277x over previous
#include <cuda_runtime.h>
#include <math.h>
#include <stdint.h>

#define NMAX 10000
#define EMAX 160000
#define NCHUNKMAX 4608

// ---------------- scratch (static device globals; no allocation) ----------------
__device__ float g_hA[NMAX * 64];
__device__ float g_hB[NMAX * 64];
__device__ float g_h256[NMAX * 256];
__device__ float g_msg[EMAX * 64];          // per-edge messages, dst-sorted slots
__device__ float g_basisE[EMAX * 8];        // basis in edge order
__device__ int   g_cellE[EMAX];
__device__ int   g_rankC[EMAX];
__device__ int   g_rankD[EMAX];
__device__ int   g_slotE[EMAX];             // dst-sorted slot, edge order
__device__ int   g_srcC[EMAX];              // src node, cell-sorted order
__device__ int   g_slotC[EMAX];             // dst-sorted slot, cell-sorted order
__device__ float g_basisC[EMAX * 8];        // basis, cell-sorted order
__device__ int   g_cellCnt[64];
__device__ int   g_cellStart[65];
__device__ int   g_deg[NMAX];
__device__ int   g_dstStart[NMAX + 1];
__device__ int   g_chunkCell[NCHUNKMAX];
__device__ int   g_chunkBeg[NCHUNKMAX];
__device__ int   g_numChunks;

// ---------------- helpers ----------------
__device__ __forceinline__ uint32_t smem_u32(const void* p) {
    uint32_t a;
    asm("{ .reg .u64 t; cvta.to.shared.u64 t, %1; cvt.u32.u64 %0, t; }" : "=r"(a) : "l"(p));
    return a;
}
__device__ __forceinline__ void cp16(uint32_t sdst, const void* gsrc) {
    asm volatile("cp.async.cg.shared.global [%0], [%1], 16;" :: "r"(sdst), "l"(gsrc));
}
__device__ __forceinline__ void cp16z(uint32_t sdst, const void* gsrc, int sz) {
    asm volatile("cp.async.cg.shared.global [%0], [%1], 16, %2;" :: "r"(sdst), "l"(gsrc), "r"(sz));
}
#define CP_COMMIT() asm volatile("cp.async.commit_group;" ::: "memory")
template <int n> __device__ __forceinline__ void cp_wait() {
    asm volatile("cp.async.wait_group %0;" :: "n"(n) : "memory");
}

// m16n8k8 tf32 mma.sync (sm_80+, valid on plain sm_100)
__device__ __forceinline__ void mma1688(float* d, uint32_t a0, uint32_t a1, uint32_t a2, uint32_t a3,
                                        uint32_t b0, uint32_t b1) {
    asm volatile(
        "mma.sync.aligned.m16n8k8.row.col.f32.tf32.tf32.f32 "
        "{%0,%1,%2,%3}, {%4,%5,%6,%7}, {%8,%9}, {%0,%1,%2,%3};"
        : "+f"(d[0]), "+f"(d[1]), "+f"(d[2]), "+f"(d[3])
        : "r"(a0), "r"(a1), "r"(a2), "r"(a3), "r"(b0), "r"(b1));
}

__device__ __forceinline__ float elu_f(float v) {
    return v > 0.0f ? v : (__expf(v) - 1.0f);
}

// ---------------- init ----------------
__global__ void k_init(int N) {
    int i = blockIdx.x * blockDim.x + threadIdx.x;
    if (i < 64) g_cellCnt[i] = 0;
    if (i < N)  g_deg[i] = 0;
}

// ---------------- per-edge: basis, cell, ranks ----------------
__global__ void k_prep(const int* __restrict__ ei, const float* __restrict__ ps, int E) {
    int e = blockIdx.x * blockDim.x + threadIdx.x;
    if (e >= E) return;
    int dst = ei[E + e];
    float fr[3];
    int lo[3];
#pragma unroll
    for (int d = 0; d < 3; d++) {
        float pos = ps[e * 3 + d] * 4.0f;   // (K-1) = 4
        float l = floorf(pos);
        l = fminf(fmaxf(l, 0.0f), 3.0f);    // clip to [0, K-2]
        lo[d] = (int)l;
        fr[d] = pos - l;
    }
    int cell = lo[0] * 16 + lo[1] * 4 + lo[2];
    g_cellE[e] = cell;
#pragma unroll
    for (int b = 0; b < 8; b++) {
        float w = 1.0f;
#pragma unroll
        for (int d = 0; d < 3; d++) w *= ((b >> d) & 1) ? fr[d] : (1.0f - fr[d]);
        g_basisE[e * 8 + b] = w;
    }
    g_rankC[e] = atomicAdd(&g_cellCnt[cell], 1);
    g_rankD[e] = atomicAdd(&g_deg[dst], 1);
}

// ---------------- scan: cell offsets, chunk list, degree prefix (single pass) ----------------
__global__ void __launch_bounds__(1024) k_scan(int N, int E) {
    __shared__ int chOff[64];
    __shared__ int warpSums[32];
    int tid = threadIdx.x;
    if (tid == 0) {
        int s = 0;
        for (int c = 0; c < 64; c++) { g_cellStart[c] = s; s += g_cellCnt[c]; }
        g_cellStart[64] = s;
        int t = 0;
        for (int c = 0; c < 64; c++) { chOff[c] = t; t += (g_cellCnt[c] + 127) / 128; }
        g_numChunks = t;
    }
    __syncthreads();
    if (tid < 64) {
        int t = chOff[tid];
        for (int b = g_cellStart[tid]; b < g_cellStart[tid + 1]; b += 128) {
            g_chunkCell[t] = tid; g_chunkBeg[t] = b; t++;
        }
    }
    // degree exclusive scan, one pass: each thread owns `per` consecutive elements
    int per = (N + 1023) / 1024;            // <= 16 assumed
    int base = tid * per;
    int lv[16];
    int s = 0;
#pragma unroll 16
    for (int i = 0; i < 16; i++) {
        if (i >= per) break;
        int v = (base + i < N) ? g_deg[base + i] : 0;
        lv[i] = s; s += v;
    }
    int lane = tid & 31, warp = tid >> 5;
    int incl = s;
#pragma unroll
    for (int off = 1; off < 32; off <<= 1) {
        int t2 = __shfl_up_sync(0xFFFFFFFF, incl, off);
        if (lane >= off) incl += t2;
    }
    if (lane == 31) warpSums[warp] = incl;
    __syncthreads();
    if (warp == 0) {
        int w = (lane < 32) ? warpSums[lane] : 0;
        int wi = w;
#pragma unroll
        for (int off = 1; off < 32; off <<= 1) {
            int t2 = __shfl_up_sync(0xFFFFFFFF, wi, off);
            if (lane >= off) wi += t2;
        }
        warpSums[lane] = wi - w;            // exclusive warp prefix
    }
    __syncthreads();
    int off0 = warpSums[warp] + (incl - s); // block-exclusive prefix for this thread
#pragma unroll 16
    for (int i = 0; i < 16; i++) {
        if (i >= per) break;
        if (base + i < N) g_dstStart[base + i] = off0 + lv[i];
    }
    if (tid == 1023) g_dstStart[N] = off0;  // last thread's exclusive prefix == total E
}

// ---------------- scatter (no atomics: ranks precomputed) ----------------
__global__ void k_scatter(const int* __restrict__ ei, int E) {
    int e = blockIdx.x * blockDim.x + threadIdx.x;
    if (e >= E) return;
    int src = ei[e], dst = ei[E + e];
    int p = g_cellStart[g_cellE[e]] + g_rankC[e];
    int q = g_dstStart[dst] + g_rankD[e];
    g_srcC[p] = src;
    g_slotC[p] = q;
    g_slotE[e] = q;
#pragma unroll
    for (int b = 0; b < 8; b++) g_basisC[p * 8 + b] = g_basisE[e * 8 + b];
}

// ---------------- tf32 mma spline-conv: 128-edge chunk x CO=64, cp.async pipelined ----------------
// 8 warps as 4(m) x 2(n); warp tile 32x32 = 2 m-atoms x 4 n-atoms of m16n8k8.
template <int CI>
__global__ void __launch_bounds__(256) k_conv_mma(const float* __restrict__ xin,
                                                  const float* __restrict__ W) {
    constexpr int XPAD = CI + 4;           // bank = (4*row + k) % 32 -> conflict-free A frags
    constexpr int WPAD = 72;               // bank = (8*k + c) % 32 -> conflict-free B frags
    constexpr int CH = CI / 2;             // floats per thread of one X row (2 thr/row)
    constexpr int WCHUNKS = CI * 16;       // 16B chunks per W tile
    extern __shared__ float sm[];
    int*   slots = (int*)sm;               // 128
    float* bsm   = sm + 128;               // 128 x 8 basis
    float* Xs    = bsm + 1024;             // 128 x XPAD
    float* Ws    = Xs + 128 * XPAD;        // 2 x (CI x WPAD)

    int bi = blockIdx.x;
    if (bi >= g_numChunks) return;
    int cell = g_chunkCell[bi];
    int beg  = g_chunkBeg[bi];
    int R = min(beg + 128, g_cellStart[cell + 1]) - beg;

    int tid = threadIdx.x, wid = tid >> 5, lid = tid & 31;
    int ix = cell >> 4, iy = (cell >> 2) & 3, iz = cell & 3;
    int kbs[8];
#pragma unroll
    for (int b = 0; b < 8; b++)
        kbs[b] = (ix + (b & 1)) * 25 + (iy + ((b >> 1) & 1)) * 5 + (iz + ((b >> 2) & 1));

    uint32_t sXs = smem_u32(Xs), sWs = smem_u32(Ws);

    {   // stage X rows via cp.async (2 threads per row), slots+basis via plain stores
        int r = tid >> 1, half = tid & 1;
        bool valid = r < R;
        if (half == 0) {
            slots[r] = valid ? g_slotC[beg + r] : -1;
#pragma unroll
            for (int b = 0; b < 8; b++)
                bsm[r * 8 + b] = valid ? g_basisC[(beg + r) * 8 + b] : 0.0f;
        }
        int src = valid ? g_srcC[beg + r] : 0;
        const float* xp = xin + (size_t)src * CI + half * CH;
        int sz = valid ? 16 : 0;
#pragma unroll
        for (int i = 0; i < CH / 4; i++)
            cp16z(sXs + (r * XPAD + half * CH + i * 4) * 4, xp + i * 4, sz);
    }
    // W prefetch: group0 = X + W[corner0], group1 = W[corner1]
    {
        const float* wp = W + (size_t)kbs[0] * CI * 64;
        for (int i = tid; i < WCHUNKS; i += 256) {
            int row = i >> 4, c4 = i & 15;
            cp16(sWs + (row * WPAD + c4 * 4) * 4, wp + row * 64 + c4 * 4);
        }
        CP_COMMIT();
        const float* wp1 = W + (size_t)kbs[1] * CI * 64;
        for (int i = tid; i < WCHUNKS; i += 256) {
            int row = i >> 4, c4 = i & 15;
            cp16(sWs + (CI * WPAD + row * WPAD + c4 * 4) * 4, wp1 + row * 64 + c4 * 4);
        }
        CP_COMMIT();
    }

    int wm = wid >> 1, wn = wid & 1;
    int g = lid >> 2, q = lid & 3;
    float acc[2][4][4];
#pragma unroll
    for (int m = 0; m < 2; m++)
#pragma unroll
        for (int n = 0; n < 4; n++)
#pragma unroll
            for (int i = 0; i < 4; i++) acc[m][n][i] = 0.0f;

#pragma unroll
    for (int b = 0; b < 8; b++) {
        if (b < 7) cp_wait<1>(); else cp_wait<0>();
        __syncthreads();

        const float* Wb = Ws + (b & 1) * CI * WPAD;
        float s0[2], s1[2];
#pragma unroll
        for (int m = 0; m < 2; m++) {
            int rr = wm * 32 + m * 16 + g;
            s0[m] = bsm[rr * 8 + b];
            s1[m] = bsm[(rr + 8) * 8 + b];
        }
#pragma unroll
        for (int ks = 0; ks < CI / 8; ks++) {
            int k0 = ks * 8;
            uint32_t B0[4], B1[4];
#pragma unroll
            for (int n = 0; n < 4; n++) {
                int c = wn * 32 + n * 8 + g;
                B0[n] = __float_as_uint(Wb[(k0 + q) * WPAD + c]);
                B1[n] = __float_as_uint(Wb[(k0 + q + 4) * WPAD + c]);
            }
#pragma unroll
            for (int m = 0; m < 2; m++) {
                int rr = wm * 32 + m * 16 + g;
                uint32_t a0 = __float_as_uint(Xs[rr * XPAD + k0 + q] * s0[m]);
                uint32_t a1 = __float_as_uint(Xs[(rr + 8) * XPAD + k0 + q] * s1[m]);
                uint32_t a2 = __float_as_uint(Xs[rr * XPAD + k0 + q + 4] * s0[m]);
                uint32_t a3 = __float_as_uint(Xs[(rr + 8) * XPAD + k0 + q + 4] * s1[m]);
#pragma unroll
                for (int n = 0; n < 4; n++)
                    mma1688(acc[m][n], a0, a1, a2, a3, B0[n], B1[n]);
            }
        }
        __syncthreads();
        if (b + 2 < 8) {    // prefetch corner b+2 into the buffer just freed
            const float* wp = W + (size_t)kbs[b + 2] * CI * 64;
            uint32_t dstb = sWs + ((b & 1) * CI * WPAD) * 4;
            for (int i = tid; i < WCHUNKS; i += 256) {
                int row = i >> 4, c4 = i & 15;
                cp16(dstb + (row * WPAD + c4 * 4) * 4, wp + row * 64 + c4 * 4);
            }
            CP_COMMIT();
        }
    }

    // store: d0/d1 at (row g, col 2q/2q+1), d2/d3 at (row g+8)
#pragma unroll
    for (int m = 0; m < 2; m++)
#pragma unroll
        for (int h = 0; h < 2; h++) {
            int row = wm * 32 + m * 16 + g + h * 8;
            int slot = slots[row];
            if (slot >= 0) {
                float* base = g_msg + (size_t)slot * 64 + wn * 32;
#pragma unroll
                for (int n = 0; n < 4; n++)
                    *(float2*)&base[n * 8 + q * 2] =
                        make_float2(acc[m][n][h * 2], acc[m][n][h * 2 + 1]);
            }
        }
}

// ---------------- layer 1 (CI=1, CO=32): warp-per-edge ----------------
__global__ void k_conv1(const float* __restrict__ x, const int* __restrict__ ei,
                        const float* __restrict__ w1, int E) {
    int e = blockIdx.x * 8 + (threadIdx.x >> 5);
    if (e >= E) return;
    int c = threadIdx.x & 31;
    int cell = g_cellE[e];
    int ix = cell >> 4, iy = (cell >> 2) & 3, iz = cell & 3;
    float acc = 0.0f;
#pragma unroll
    for (int b = 0; b < 8; b++) {
        int kb = (ix + (b & 1)) * 25 + (iy + ((b >> 1) & 1)) * 5 + (iz + ((b >> 2) & 1));
        acc += g_basisE[e * 8 + b] * w1[kb * 32 + c];
    }
    g_msg[(size_t)g_slotE[e] * 32 + c] = x[ei[e]] * acc;
}

// ---------------- segmented mean + root + bias + ELU ----------------
template <int CI, int CO>
__global__ void k_conv_reduce(const float* __restrict__ xin, const float* __restrict__ root,
                              const float* __restrict__ bias, float* __restrict__ xout, int N) {
    constexpr int NPB = 128 / CO;
    int n = blockIdx.x * NPB + threadIdx.x / CO;
    int j = threadIdx.x % CO;
    if (n >= N) return;
    int s0 = g_dstStart[n], s1 = g_dstStart[n + 1];
    float s = 0.0f;
    for (int r = s0; r < s1; r++) s += g_msg[(size_t)r * CO + j];
    float d = (float)max(g_deg[n], 1);
    float rt = 0.0f;
#pragma unroll 8
    for (int ci = 0; ci < CI; ci++) rt += xin[n * CI + ci] * root[ci * CO + j];
    float v = s / d + rt + bias[j];
    xout[(size_t)n * CO + j] = elu_f(v);
}

// ---------------- FC GEMM via tf32 mma: block 64x128, warp 32x32, cp.async pipelined ----------------
template <int KD, bool DOELU>
__global__ void __launch_bounds__(256) k_fc_mma(const float* __restrict__ A,
                                                const float* __restrict__ B,
                                                const float* __restrict__ bias,
                                                float* __restrict__ C, int M, int NC) {
    constexpr int APAD = 68, BPAD = 136;
    constexpr int NIT = KD / 64;
    extern __shared__ float sm[];
    float* As = sm;                         // 2 x 64 x APAD
    float* Bs = sm + 2 * 64 * APAD;         // 2 x 64 x BPAD
    uint32_t sAs = smem_u32(As), sBs = smem_u32(Bs);
    int rb = blockIdx.x * 64, cb = blockIdx.y * 128;
    int tid = threadIdx.x, wid = tid >> 5, lid = tid & 31;
    int wm = wid >> 2, wn = wid & 3;        // 2 x 4 warps
    int g = lid >> 2, q = lid & 3;

    auto stage = [&](int it, int buf) {
        int kc = it * 64;
        for (int i = tid; i < 1024; i += 256) {     // A tile 64x64
            int row = i >> 4, c4 = i & 15;
            int gr = rb + row;
            cp16z(sAs + (buf * 64 * APAD + row * APAD + c4 * 4) * 4,
                  A + (size_t)min(gr, M - 1) * KD + kc + c4 * 4, (gr < M) ? 16 : 0);
        }
        for (int i = tid; i < 2048; i += 256) {     // B tile 64x128
            int row = i >> 5, c4 = i & 31;
            cp16(sBs + (buf * 64 * BPAD + row * BPAD + c4 * 4) * 4,
                 B + (size_t)(kc + row) * NC + cb + c4 * 4);
        }
        CP_COMMIT();
    };

    float acc[2][4][4];
#pragma unroll
    for (int m = 0; m < 2; m++)
#pragma unroll
        for (int n = 0; n < 4; n++)
#pragma unroll
            for (int i = 0; i < 4; i++) acc[m][n][i] = 0.0f;

    stage(0, 0);
    if (NIT > 1) stage(1, 1);

#pragma unroll
    for (int it = 0; it < NIT; it++) {
        if (it + 1 < NIT) cp_wait<1>(); else cp_wait<0>();
        __syncthreads();
        const float* Ab = As + (it & 1) * 64 * APAD;
        const float* Bb = Bs + (it & 1) * 64 * BPAD;
#pragma unroll
        for (int ks = 0; ks < 8; ks++) {
            int k0 = ks * 8;
            uint32_t B0[4], B1[4];
#pragma unroll
            for (int n = 0; n < 4; n++) {
                int c = wn * 32 + n * 8 + g;
                B0[n] = __float_as_uint(Bb[(k0 + q) * BPAD + c]);
                B1[n] = __float_as_uint(Bb[(k0 + q + 4) * BPAD + c]);
            }
#pragma unroll
            for (int m = 0; m < 2; m++) {
                int rr = wm * 32 + m * 16 + g;
                uint32_t a0 = __float_as_uint(Ab[rr * APAD + k0 + q]);
                uint32_t a1 = __float_as_uint(Ab[(rr + 8) * APAD + k0 + q]);
                uint32_t a2 = __float_as_uint(Ab[rr * APAD + k0 + q + 4]);
                uint32_t a3 = __float_as_uint(Ab[(rr + 8) * APAD + k0 + q + 4]);
#pragma unroll
                for (int n = 0; n < 4; n++)
                    mma1688(acc[m][n], a0, a1, a2, a3, B0[n], B1[n]);
            }
        }
        __syncthreads();
        if (it + 2 < NIT) stage(it + 2, it & 1);
    }

#pragma unroll
    for (int m = 0; m < 2; m++)
#pragma unroll
        for (int h = 0; h < 2; h++) {
            int gr = rb + wm * 32 + m * 16 + g + h * 8;
            if (gr >= M) continue;
#pragma unroll
            for (int n = 0; n < 4; n++) {
                int col = cb + wn * 32 + n * 8 + q * 2;
                float v0 = acc[m][n][h * 2] + bias[col];
                float v1 = acc[m][n][h * 2 + 1] + bias[col + 1];
                if (DOELU) { v0 = elu_f(v0); v1 = elu_f(v1); }
                *(float2*)&C[(size_t)gr * NC + col] = make_float2(v0, v1);
            }
        }
}

// ---------------- log_softmax over 1024 cols, in place ----------------
__global__ void k_lsm(float* __restrict__ out) {
    __shared__ float red[256];
    int n = blockIdx.x;
    float* row = out + (size_t)n * 1024;
    int tid = threadIdx.x;
    float v[4];
    float m = -INFINITY;
#pragma unroll
    for (int i = 0; i < 4; i++) { v[i] = row[tid + 256 * i]; m = fmaxf(m, v[i]); }
    red[tid] = m;
    __syncthreads();
    for (int off = 128; off; off >>= 1) {
        if (tid < off) red[tid] = fmaxf(red[tid], red[tid + off]);
        __syncthreads();
    }
    m = red[0];
    __syncthreads();
    float s = 0.0f;
#pragma unroll
    for (int i = 0; i < 4; i++) s += __expf(v[i] - m);
    red[tid] = s;
    __syncthreads();
    for (int off = 128; off; off >>= 1) {
        if (tid < off) red[tid] += red[tid + off];
        __syncthreads();
    }
    float l = m + __logf(red[0]);
#pragma unroll
    for (int i = 0; i < 4; i++) row[tid + 256 * i] = v[i] - l;
}

// ---------------- launcher ----------------
extern "C" void kernel_launch(void* const* d_in, const int* in_sizes, int n_in,
                              void* d_out, int out_size) {
    const float* x      = (const float*)d_in[0];
    const int*   ei     = (const int*)d_in[1];
    const float* pseudo = (const float*)d_in[2];
    const float *w[6], *root[6], *bias[6];
    for (int i = 0; i < 6; i++) {
        w[i]    = (const float*)d_in[3 + 3 * i];
        root[i] = (const float*)d_in[4 + 3 * i];
        bias[i] = (const float*)d_in[5 + 3 * i];
    }
    const float* fc1w = (const float*)d_in[21];
    const float* fc1b = (const float*)d_in[22];
    const float* fc2w = (const float*)d_in[23];
    const float* fc2b = (const float*)d_in[24];
    float* out = (float*)d_out;

    int N = in_sizes[0];
    int E = in_sizes[1] / 2;

    int eg = (E + 255) / 256;
    int ng = (N + 255) / 256;
    int nchunks = (E + 127) / 128 + 64;

    float* hA = nullptr; cudaGetSymbolAddress((void**)&hA, g_hA);
    float* hB = nullptr; cudaGetSymbolAddress((void**)&hB, g_hB);
    float* h256 = nullptr; cudaGetSymbolAddress((void**)&h256, g_h256);

    // dynamic smem sizes (floats*4): slots 128, basis 1024, X 128*XPAD, W 2*CI*WPAD
    constexpr int CSM64 = (128 + 1024 + 128 * 68 + 2 * 64 * 72) * 4;   // 76288
    constexpr int CSM32 = (128 + 1024 + 128 * 36 + 2 * 32 * 72) * 4;   // 41472
    constexpr int FSM   = (2 * 64 * 68 + 2 * 64 * 136) * 4;            // 104448
    cudaFuncSetAttribute(k_conv_mma<64>, cudaFuncAttributeMaxDynamicSharedMemorySize, CSM64);
    cudaFuncSetAttribute(k_conv_mma<32>, cudaFuncAttributeMaxDynamicSharedMemorySize, CSM32);
    cudaFuncSetAttribute(k_fc_mma<64, true>, cudaFuncAttributeMaxDynamicSharedMemorySize, FSM);
    cudaFuncSetAttribute(k_fc_mma<256, false>, cudaFuncAttributeMaxDynamicSharedMemorySize, FSM);

    k_init<<<ng, 256>>>(N);
    k_prep<<<eg, 256>>>(ei, pseudo, E);
    k_scan<<<1, 1024>>>(N, E);
    k_scatter<<<eg, 256>>>(ei, E);

    // layer 1: 1 -> 32 (SIMT, warp per edge)
    k_conv1<<<(E + 7) / 8, 256>>>(x, ei, w[0], E);
    k_conv_reduce<1, 32><<<(N + 3) / 4, 128>>>(x, root[0], bias[0], hA, N);
    // layer 2: 32 -> 64 (tf32 mma)
    k_conv_mma<32><<<nchunks, 256, CSM32>>>(hA, w[1]);
    k_conv_reduce<32, 64><<<(N + 1) / 2, 128>>>(hA, root[1], bias[1], hB, N);
    // layers 3-6: 64 -> 64 (tf32 mma)
    k_conv_mma<64><<<nchunks, 256, CSM64>>>(hB, w[2]);
    k_conv_reduce<64, 64><<<(N + 1) / 2, 128>>>(hB, root[2], bias[2], hA, N);
    k_conv_mma<64><<<nchunks, 256, CSM64>>>(hA, w[3]);
    k_conv_reduce<64, 64><<<(N + 1) / 2, 128>>>(hA, root[3], bias[3], hB, N);
    k_conv_mma<64><<<nchunks, 256, CSM64>>>(hB, w[4]);
    k_conv_reduce<64, 64><<<(N + 1) / 2, 128>>>(hB, root[4], bias[4], hA, N);
    k_conv_mma<64><<<nchunks, 256, CSM64>>>(hA, w[5]);
    k_conv_reduce<64, 64><<<(N + 1) / 2, 128>>>(hA, root[5], bias[5], hB, N);

    // fc1: [N,64] @ [64,256] + ELU
    k_fc_mma<64, true><<<dim3((N + 63) / 64, 2), 256, FSM>>>(hB, fc1w, fc1b, h256, N, 256);
    // fc2: [N,256] @ [256,1024]
    k_fc_mma<256, false><<<dim3((N + 63) / 64, 8), 256, FSM>>>(h256, fc2w, fc2b, out, N, 1024);
    // log_softmax in place
    k_lsm<<<N, 256>>>(out);
}

// round 8
// speedup vs baseline: 3.0266x; 1.0246x over previous
#include <cuda_runtime.h>
#include <cuda_fp16.h>
#include <math.h>
#include <stdint.h>

#define NMAX 10000
#define EMAX 160000
#define NCHUNKMAX 4608

// ---------------- scratch (static device globals; no allocation) ----------------
__device__ float  g_hA[NMAX * 64];
__device__ float  g_hB[NMAX * 64];
__device__ float  g_h256[NMAX * 256];
__device__ float  g_root[NMAX * 64];         // per-layer x@root + bias
__device__ __half g_msgh[EMAX * 64];         // per-edge messages (fp16), dst-sorted slots
__device__ float  g_basisE[EMAX * 8];
__device__ int    g_cellE[EMAX];
__device__ int    g_rankC[EMAX];
__device__ int    g_rankD[EMAX];
__device__ int    g_slotE[EMAX];
__device__ int    g_srcC[EMAX];
__device__ int    g_slotC[EMAX];
__device__ float  g_basisC[EMAX * 8];
__device__ int    g_cellCnt[64];
__device__ int    g_cellStart[65];
__device__ int    g_deg[NMAX];
__device__ int    g_dstStart[NMAX + 1];
__device__ int    g_chunkCell[NCHUNKMAX];
__device__ int    g_chunkBeg[NCHUNKMAX];
__device__ int    g_numChunks;

// ---------------- helpers ----------------
__device__ __forceinline__ uint32_t smem_u32(const void* p) {
    uint32_t a;
    asm("{ .reg .u64 t; cvta.to.shared.u64 t, %1; cvt.u32.u64 %0, t; }" : "=r"(a) : "l"(p));
    return a;
}
__device__ __forceinline__ void cp16(uint32_t sdst, const void* gsrc) {
    asm volatile("cp.async.cg.shared.global [%0], [%1], 16;" :: "r"(sdst), "l"(gsrc));
}
__device__ __forceinline__ void cp16z(uint32_t sdst, const void* gsrc, int sz) {
    asm volatile("cp.async.cg.shared.global [%0], [%1], 16, %2;" :: "r"(sdst), "l"(gsrc), "r"(sz));
}
#define CP_COMMIT() asm volatile("cp.async.commit_group;" ::: "memory")
template <int n> __device__ __forceinline__ void cp_wait() {
    asm volatile("cp.async.wait_group %0;" :: "n"(n) : "memory");
}

__device__ __forceinline__ void mma1688(float* d, uint32_t a0, uint32_t a1, uint32_t a2, uint32_t a3,
                                        uint32_t b0, uint32_t b1) {
    asm volatile(
        "mma.sync.aligned.m16n8k8.row.col.f32.tf32.tf32.f32 "
        "{%0,%1,%2,%3}, {%4,%5,%6,%7}, {%8,%9}, {%0,%1,%2,%3};"
        : "+f"(d[0]), "+f"(d[1]), "+f"(d[2]), "+f"(d[3])
        : "r"(a0), "r"(a1), "r"(a2), "r"(a3), "r"(b0), "r"(b1));
}

__device__ __forceinline__ float elu_f(float v) {
    return v > 0.0f ? v : (__expf(v) - 1.0f);
}

// ---------------- init ----------------
__global__ void k_init(int N) {
    int i = blockIdx.x * blockDim.x + threadIdx.x;
    if (i < 64) g_cellCnt[i] = 0;
    if (i < N)  g_deg[i] = 0;
}

// ---------------- per-edge: basis, cell, ranks ----------------
__global__ void k_prep(const int* __restrict__ ei, const float* __restrict__ ps, int E) {
    int e = blockIdx.x * blockDim.x + threadIdx.x;
    if (e >= E) return;
    int dst = ei[E + e];
    float fr[3];
    int lo[3];
#pragma unroll
    for (int d = 0; d < 3; d++) {
        float pos = ps[e * 3 + d] * 4.0f;
        float l = floorf(pos);
        l = fminf(fmaxf(l, 0.0f), 3.0f);
        lo[d] = (int)l;
        fr[d] = pos - l;
    }
    int cell = lo[0] * 16 + lo[1] * 4 + lo[2];
    g_cellE[e] = cell;
#pragma unroll
    for (int b = 0; b < 8; b++) {
        float w = 1.0f;
#pragma unroll
        for (int d = 0; d < 3; d++) w *= ((b >> d) & 1) ? fr[d] : (1.0f - fr[d]);
        g_basisE[e * 8 + b] = w;
    }
    g_rankC[e] = atomicAdd(&g_cellCnt[cell], 1);
    g_rankD[e] = atomicAdd(&g_deg[dst], 1);
}

// ---------------- scan: cell offsets, chunk list, degree prefix (single pass) ----------------
__global__ void __launch_bounds__(1024) k_scan(int N, int E) {
    __shared__ int chOff[64];
    __shared__ int warpSums[32];
    int tid = threadIdx.x;
    if (tid == 0) {
        int s = 0;
        for (int c = 0; c < 64; c++) { g_cellStart[c] = s; s += g_cellCnt[c]; }
        g_cellStart[64] = s;
        int t = 0;
        for (int c = 0; c < 64; c++) { chOff[c] = t; t += (g_cellCnt[c] + 127) / 128; }
        g_numChunks = t;
    }
    __syncthreads();
    if (tid < 64) {
        int t = chOff[tid];
        for (int b = g_cellStart[tid]; b < g_cellStart[tid + 1]; b += 128) {
            g_chunkCell[t] = tid; g_chunkBeg[t] = b; t++;
        }
    }
    int per = (N + 1023) / 1024;
    int base = tid * per;
    int lv[16];
    int s = 0;
#pragma unroll 16
    for (int i = 0; i < 16; i++) {
        if (i >= per) break;
        int v = (base + i < N) ? g_deg[base + i] : 0;
        lv[i] = s; s += v;
    }
    int lane = tid & 31, warp = tid >> 5;
    int incl = s;
#pragma unroll
    for (int off = 1; off < 32; off <<= 1) {
        int t2 = __shfl_up_sync(0xFFFFFFFF, incl, off);
        if (lane >= off) incl += t2;
    }
    if (lane == 31) warpSums[warp] = incl;
    __syncthreads();
    if (warp == 0) {
        int w = (lane < 32) ? warpSums[lane] : 0;
        int wi = w;
#pragma unroll
        for (int off = 1; off < 32; off <<= 1) {
            int t2 = __shfl_up_sync(0xFFFFFFFF, wi, off);
            if (lane >= off) wi += t2;
        }
        warpSums[lane] = wi - w;
    }
    __syncthreads();
    int off0 = warpSums[warp] + (incl - s);
#pragma unroll 16
    for (int i = 0; i < 16; i++) {
        if (i >= per) break;
        if (base + i < N) g_dstStart[base + i] = off0 + lv[i];
    }
    if (tid == 1023) g_dstStart[N] = off0;
}

// ---------------- scatter ----------------
__global__ void k_scatter(const int* __restrict__ ei, int E) {
    int e = blockIdx.x * blockDim.x + threadIdx.x;
    if (e >= E) return;
    int src = ei[e], dst = ei[E + e];
    int p = g_cellStart[g_cellE[e]] + g_rankC[e];
    int q = g_dstStart[dst] + g_rankD[e];
    g_srcC[p] = src;
    g_slotC[p] = q;
    g_slotE[e] = q;
#pragma unroll
    for (int b = 0; b < 8; b++) g_basisC[p * 8 + b] = g_basisE[e * 8 + b];
}

// ---------------- tf32 mma spline-conv ----------------
template <int CI>
__global__ void __launch_bounds__(256) k_conv_mma(const float* __restrict__ xin,
                                                  const float* __restrict__ W) {
    constexpr int XPAD = CI + 4;
    constexpr int WPAD = 72;
    constexpr int CH = CI / 2;
    constexpr int WCHUNKS = CI * 16;
    extern __shared__ float sm[];
    int*   slots = (int*)sm;
    float* bsm   = sm + 128;
    float* Xs    = bsm + 1024;
    float* Ws    = Xs + 128 * XPAD;

    int bi = blockIdx.x;
    if (bi >= g_numChunks) return;
    int cell = g_chunkCell[bi];
    int beg  = g_chunkBeg[bi];
    int R = min(beg + 128, g_cellStart[cell + 1]) - beg;

    int tid = threadIdx.x, wid = tid >> 5, lid = tid & 31;
    int ix = cell >> 4, iy = (cell >> 2) & 3, iz = cell & 3;
    int kbs[8];
#pragma unroll
    for (int b = 0; b < 8; b++)
        kbs[b] = (ix + (b & 1)) * 25 + (iy + ((b >> 1) & 1)) * 5 + (iz + ((b >> 2) & 1));

    uint32_t sXs = smem_u32(Xs), sWs = smem_u32(Ws);

    {
        int r = tid >> 1, half = tid & 1;
        bool valid = r < R;
        if (half == 0) {
            slots[r] = valid ? g_slotC[beg + r] : -1;
#pragma unroll
            for (int b = 0; b < 8; b++)
                bsm[r * 8 + b] = valid ? g_basisC[(beg + r) * 8 + b] : 0.0f;
        }
        int src = valid ? g_srcC[beg + r] : 0;
        const float* xp = xin + (size_t)src * CI + half * CH;
        int sz = valid ? 16 : 0;
#pragma unroll
        for (int i = 0; i < CH / 4; i++)
            cp16z(sXs + (r * XPAD + half * CH + i * 4) * 4, xp + i * 4, sz);
    }
    {
        const float* wp = W + (size_t)kbs[0] * CI * 64;
        for (int i = tid; i < WCHUNKS; i += 256) {
            int row = i >> 4, c4 = i & 15;
            cp16(sWs + (row * WPAD + c4 * 4) * 4, wp + row * 64 + c4 * 4);
        }
        CP_COMMIT();
        const float* wp1 = W + (size_t)kbs[1] * CI * 64;
        for (int i = tid; i < WCHUNKS; i += 256) {
            int row = i >> 4, c4 = i & 15;
            cp16(sWs + (CI * WPAD + row * WPAD + c4 * 4) * 4, wp1 + row * 64 + c4 * 4);
        }
        CP_COMMIT();
    }

    int wm = wid >> 1, wn = wid & 1;
    int g = lid >> 2, q = lid & 3;
    float acc[2][4][4];
#pragma unroll
    for (int m = 0; m < 2; m++)
#pragma unroll
        for (int n = 0; n < 4; n++)
#pragma unroll
            for (int i = 0; i < 4; i++) acc[m][n][i] = 0.0f;

#pragma unroll
    for (int b = 0; b < 8; b++) {
        if (b < 7) cp_wait<1>(); else cp_wait<0>();
        __syncthreads();

        const float* Wb = Ws + (b & 1) * CI * WPAD;
        float s0[2], s1[2];
#pragma unroll
        for (int m = 0; m < 2; m++) {
            int rr = wm * 32 + m * 16 + g;
            s0[m] = bsm[rr * 8 + b];
            s1[m] = bsm[(rr + 8) * 8 + b];
        }
#pragma unroll
        for (int ks = 0; ks < CI / 8; ks++) {
            int k0 = ks * 8;
            uint32_t B0[4], B1[4];
#pragma unroll
            for (int n = 0; n < 4; n++) {
                int c = wn * 32 + n * 8 + g;
                B0[n] = __float_as_uint(Wb[(k0 + q) * WPAD + c]);
                B1[n] = __float_as_uint(Wb[(k0 + q + 4) * WPAD + c]);
            }
#pragma unroll
            for (int m = 0; m < 2; m++) {
                int rr = wm * 32 + m * 16 + g;
                uint32_t a0 = __float_as_uint(Xs[rr * XPAD + k0 + q] * s0[m]);
                uint32_t a1 = __float_as_uint(Xs[(rr + 8) * XPAD + k0 + q] * s1[m]);
                uint32_t a2 = __float_as_uint(Xs[rr * XPAD + k0 + q + 4] * s0[m]);
                uint32_t a3 = __float_as_uint(Xs[(rr + 8) * XPAD + k0 + q + 4] * s1[m]);
#pragma unroll
                for (int n = 0; n < 4; n++)
                    mma1688(acc[m][n], a0, a1, a2, a3, B0[n], B1[n]);
            }
        }
        __syncthreads();
        if (b + 2 < 8) {
            const float* wp = W + (size_t)kbs[b + 2] * CI * 64;
            uint32_t dstb = sWs + ((b & 1) * CI * WPAD) * 4;
            for (int i = tid; i < WCHUNKS; i += 256) {
                int row = i >> 4, c4 = i & 15;
                cp16(dstb + (row * WPAD + c4 * 4) * 4, wp + row * 64 + c4 * 4);
            }
            CP_COMMIT();
        }
    }

#pragma unroll
    for (int m = 0; m < 2; m++)
#pragma unroll
        for (int h = 0; h < 2; h++) {
            int row = wm * 32 + m * 16 + g + h * 8;
            int slot = slots[row];
            if (slot >= 0) {
                __half2* base = (__half2*)(g_msgh + (size_t)slot * 64 + wn * 32);
#pragma unroll
                for (int n = 0; n < 4; n++)
                    base[(n * 8 + q * 2) >> 1] =
                        __floats2half2_rn(acc[m][n][h * 2], acc[m][n][h * 2 + 1]);
            }
        }
}

// ---------------- layer 1 (CI=1, CO=32) ----------------
__global__ void k_conv1(const float* __restrict__ x, const int* __restrict__ ei,
                        const float* __restrict__ w1, int E) {
    int e = blockIdx.x * 8 + (threadIdx.x >> 5);
    if (e >= E) return;
    int c = threadIdx.x & 31;
    int cell = g_cellE[e];
    int ix = cell >> 4, iy = (cell >> 2) & 3, iz = cell & 3;
    float acc = 0.0f;
#pragma unroll
    for (int b = 0; b < 8; b++) {
        int kb = (ix + (b & 1)) * 25 + (iy + ((b >> 1) & 1)) * 5 + (iz + ((b >> 2) & 1));
        acc += g_basisE[e * 8 + b] * w1[kb * 32 + c];
    }
    g_msgh[(size_t)g_slotE[e] * 32 + c] = __float2half(x[ei[e]] * acc);
}

// ---------------- root GEMM: out = X @ root + bias (NC=64, single K tile) ----------------
template <int CI>
__global__ void __launch_bounds__(128) k_root(const float* __restrict__ X,
                                              const float* __restrict__ root,
                                              const float* __restrict__ bias,
                                              float* __restrict__ out, int M) {
    constexpr int APAD = CI + 4, WPAD = 72;
    extern __shared__ float sm[];
    float* As = sm;
    float* Bs = sm + 64 * APAD;
    uint32_t sAs = smem_u32(As), sBs = smem_u32(Bs);
    int rb = blockIdx.x * 64;
    int tid = threadIdx.x, wid = tid >> 5, lid = tid & 31;
    int wm = wid >> 1, wn = wid & 1;
    int g = lid >> 2, q = lid & 3;

    constexpr int ACH = 64 * CI / 4;
    for (int i = tid; i < ACH; i += 128) {
        int row = i / (CI / 4), c4 = i % (CI / 4);
        int gr = rb + row;
        cp16z(sAs + (row * APAD + c4 * 4) * 4,
              X + (size_t)min(gr, M - 1) * CI + c4 * 4, (gr < M) ? 16 : 0);
    }
    for (int i = tid; i < CI * 16; i += 128) {
        int row = i >> 4, c4 = i & 15;
        cp16(sBs + (row * WPAD + c4 * 4) * 4, root + row * 64 + c4 * 4);
    }
    CP_COMMIT();
    cp_wait<0>();
    __syncthreads();

    float acc[2][4][4];
#pragma unroll
    for (int m = 0; m < 2; m++)
#pragma unroll
        for (int n = 0; n < 4; n++)
#pragma unroll
            for (int i = 0; i < 4; i++) acc[m][n][i] = 0.0f;

#pragma unroll
    for (int ks = 0; ks < CI / 8; ks++) {
        int k0 = ks * 8;
        uint32_t B0[4], B1[4];
#pragma unroll
        for (int n = 0; n < 4; n++) {
            int c = wn * 32 + n * 8 + g;
            B0[n] = __float_as_uint(Bs[(k0 + q) * WPAD + c]);
            B1[n] = __float_as_uint(Bs[(k0 + q + 4) * WPAD + c]);
        }
#pragma unroll
        for (int m = 0; m < 2; m++) {
            int rr = wm * 32 + m * 16 + g;
            uint32_t a0 = __float_as_uint(As[rr * APAD + k0 + q]);
            uint32_t a1 = __float_as_uint(As[(rr + 8) * APAD + k0 + q]);
            uint32_t a2 = __float_as_uint(As[rr * APAD + k0 + q + 4]);
            uint32_t a3 = __float_as_uint(As[(rr + 8) * APAD + k0 + q + 4]);
#pragma unroll
            for (int n = 0; n < 4; n++)
                mma1688(acc[m][n], a0, a1, a2, a3, B0[n], B1[n]);
        }
    }

#pragma unroll
    for (int m = 0; m < 2; m++)
#pragma unroll
        for (int h = 0; h < 2; h++) {
            int gr = rb + wm * 32 + m * 16 + g + h * 8;
            if (gr >= M) continue;
#pragma unroll
            for (int n = 0; n < 4; n++) {
                int col = wn * 32 + n * 8 + q * 2;
                float2 bv = *(const float2*)&bias[col];
                *(float2*)&out[(size_t)gr * 64 + col] =
                    make_float2(acc[m][n][h * 2] + bv.x, acc[m][n][h * 2 + 1] + bv.y);
            }
        }
}

// ---------------- light reduce (CO=64): mean(msg) + rootbuf, ELU ----------------
__global__ void __launch_bounds__(256) k_reduceL(const float* __restrict__ rootb,
                                                 float* __restrict__ xout, int N) {
    int n = blockIdx.x * 8 + (threadIdx.x >> 5);
    if (n >= N) return;
    int jp = threadIdx.x & 31;
    int s0 = g_dstStart[n], s1 = g_dstStart[n + 1];
    float sx = 0.0f, sy = 0.0f;
    for (int r = s0; r < s1; r++) {
        float2 v = __half22float2(((const __half2*)(g_msgh + (size_t)r * 64))[jp]);
        sx += v.x; sy += v.y;
    }
    float inv = 1.0f / (float)max(g_deg[n], 1);
    float2 rb = *(const float2*)&rootb[(size_t)n * 64 + jp * 2];
    *(float2*)&xout[(size_t)n * 64 + jp * 2] =
        make_float2(elu_f(sx * inv + rb.x), elu_f(sy * inv + rb.y));
}

// ---------------- layer-1 reduce (CI=1, CO=32), root inline ----------------
__global__ void __launch_bounds__(256) k_reduce1(const float* __restrict__ x,
                                                 const float* __restrict__ root1,
                                                 const float* __restrict__ b1,
                                                 float* __restrict__ xout, int N) {
    int n = blockIdx.x * 16 + (threadIdx.x >> 4);
    if (n >= N) return;
    int jp = threadIdx.x & 15;
    int s0 = g_dstStart[n], s1 = g_dstStart[n + 1];
    float sx = 0.0f, sy = 0.0f;
    for (int r = s0; r < s1; r++) {
        float2 v = __half22float2(((const __half2*)(g_msgh + (size_t)r * 32))[jp]);
        sx += v.x; sy += v.y;
    }
    float inv = 1.0f / (float)max(g_deg[n], 1);
    float xn = x[n];
    float2 rv = *(const float2*)&root1[jp * 2];
    float2 bv = *(const float2*)&b1[jp * 2];
    *(float2*)&xout[(size_t)n * 32 + jp * 2] =
        make_float2(elu_f(sx * inv + xn * rv.x + bv.x), elu_f(sy * inv + xn * rv.y + bv.y));
}

// ---------------- FC GEMM (block 64x128, cp.async pipelined) ----------------
template <int KD, bool DOELU>
__global__ void __launch_bounds__(256) k_fc_mma(const float* __restrict__ A,
                                                const float* __restrict__ B,
                                                const float* __restrict__ bias,
                                                float* __restrict__ C, int M, int NC) {
    constexpr int APAD = 68, BPAD = 136;
    constexpr int NIT = KD / 64;
    extern __shared__ float sm[];
    float* As = sm;
    float* Bs = sm + 2 * 64 * APAD;
    uint32_t sAs = smem_u32(As), sBs = smem_u32(Bs);
    int rb = blockIdx.x * 64, cb = blockIdx.y * 128;
    int tid = threadIdx.x, wid = tid >> 5, lid = tid & 31;
    int wm = wid >> 2, wn = wid & 3;
    int g = lid >> 2, q = lid & 3;

    auto stage = [&](int it, int buf) {
        int kc = it * 64;
        for (int i = tid; i < 1024; i += 256) {
            int row = i >> 4, c4 = i & 15;
            int gr = rb + row;
            cp16z(sAs + (buf * 64 * APAD + row * APAD + c4 * 4) * 4,
                  A + (size_t)min(gr, M - 1) * KD + kc + c4 * 4, (gr < M) ? 16 : 0);
        }
        for (int i = tid; i < 2048; i += 256) {
            int row = i >> 5, c4 = i & 31;
            cp16(sBs + (buf * 64 * BPAD + row * BPAD + c4 * 4) * 4,
                 B + (size_t)(kc + row) * NC + cb + c4 * 4);
        }
        CP_COMMIT();
    };

    float acc[2][4][4];
#pragma unroll
    for (int m = 0; m < 2; m++)
#pragma unroll
        for (int n = 0; n < 4; n++)
#pragma unroll
            for (int i = 0; i < 4; i++) acc[m][n][i] = 0.0f;

    stage(0, 0);
    if (NIT > 1) stage(1, 1);

#pragma unroll
    for (int it = 0; it < NIT; it++) {
        if (it + 1 < NIT) cp_wait<1>(); else cp_wait<0>();
        __syncthreads();
        const float* Ab = As + (it & 1) * 64 * APAD;
        const float* Bb = Bs + (it & 1) * 64 * BPAD;
#pragma unroll
        for (int ks = 0; ks < 8; ks++) {
            int k0 = ks * 8;
            uint32_t B0[4], B1[4];
#pragma unroll
            for (int n = 0; n < 4; n++) {
                int c = wn * 32 + n * 8 + g;
                B0[n] = __float_as_uint(Bb[(k0 + q) * BPAD + c]);
                B1[n] = __float_as_uint(Bb[(k0 + q + 4) * BPAD + c]);
            }
#pragma unroll
            for (int m = 0; m < 2; m++) {
                int rr = wm * 32 + m * 16 + g;
                uint32_t a0 = __float_as_uint(Ab[rr * APAD + k0 + q]);
                uint32_t a1 = __float_as_uint(Ab[(rr + 8) * APAD + k0 + q]);
                uint32_t a2 = __float_as_uint(Ab[rr * APAD + k0 + q + 4]);
                uint32_t a3 = __float_as_uint(Ab[(rr + 8) * APAD + k0 + q + 4]);
#pragma unroll
                for (int n = 0; n < 4; n++)
                    mma1688(acc[m][n], a0, a1, a2, a3, B0[n], B1[n]);
            }
        }
        __syncthreads();
        if (it + 2 < NIT) stage(it + 2, it & 1);
    }

#pragma unroll
    for (int m = 0; m < 2; m++)
#pragma unroll
        for (int h = 0; h < 2; h++) {
            int gr = rb + wm * 32 + m * 16 + g + h * 8;
            if (gr >= M) continue;
#pragma unroll
            for (int n = 0; n < 4; n++) {
                int col = cb + wn * 32 + n * 8 + q * 2;
                float v0 = acc[m][n][h * 2] + bias[col];
                float v1 = acc[m][n][h * 2 + 1] + bias[col + 1];
                if (DOELU) { v0 = elu_f(v0); v1 = elu_f(v1); }
                *(float2*)&C[(size_t)gr * NC + col] = make_float2(v0, v1);
            }
        }
}

// ---------------- log_softmax ----------------
__global__ void k_lsm(float* __restrict__ out) {
    __shared__ float red[256];
    int n = blockIdx.x;
    float* row = out + (size_t)n * 1024;
    int tid = threadIdx.x;
    float v[4];
    float m = -INFINITY;
#pragma unroll
    for (int i = 0; i < 4; i++) { v[i] = row[tid + 256 * i]; m = fmaxf(m, v[i]); }
    red[tid] = m;
    __syncthreads();
    for (int off = 128; off; off >>= 1) {
        if (tid < off) red[tid] = fmaxf(red[tid], red[tid + off]);
        __syncthreads();
    }
    m = red[0];
    __syncthreads();
    float s = 0.0f;
#pragma unroll
    for (int i = 0; i < 4; i++) s += __expf(v[i] - m);
    red[tid] = s;
    __syncthreads();
    for (int off = 128; off; off >>= 1) {
        if (tid < off) red[tid] += red[tid + off];
        __syncthreads();
    }
    float l = m + __logf(red[0]);
#pragma unroll
    for (int i = 0; i < 4; i++) row[tid + 256 * i] = v[i] - l;
}

// ---------------- launcher ----------------
extern "C" void kernel_launch(void* const* d_in, const int* in_sizes, int n_in,
                              void* d_out, int out_size) {
    const float* x      = (const float*)d_in[0];
    const int*   ei     = (const int*)d_in[1];
    const float* pseudo = (const float*)d_in[2];
    const float *w[6], *root[6], *bias[6];
    for (int i = 0; i < 6; i++) {
        w[i]    = (const float*)d_in[3 + 3 * i];
        root[i] = (const float*)d_in[4 + 3 * i];
        bias[i] = (const float*)d_in[5 + 3 * i];
    }
    const float* fc1w = (const float*)d_in[21];
    const float* fc1b = (const float*)d_in[22];
    const float* fc2w = (const float*)d_in[23];
    const float* fc2b = (const float*)d_in[24];
    float* out = (float*)d_out;

    int N = in_sizes[0];
    int E = in_sizes[1] / 2;

    int eg = (E + 255) / 256;
    int ng = (N + 255) / 256;
    int nchunks = (E + 127) / 128 + 64;
    int nb64 = (N + 63) / 64;

    float* hA = nullptr; cudaGetSymbolAddress((void**)&hA, g_hA);
    float* hB = nullptr; cudaGetSymbolAddress((void**)&hB, g_hB);
    float* h256 = nullptr; cudaGetSymbolAddress((void**)&h256, g_h256);
    float* rtb = nullptr; cudaGetSymbolAddress((void**)&rtb, g_root);

    constexpr int CSM64 = (128 + 1024 + 128 * 68 + 2 * 64 * 72) * 4;
    constexpr int CSM32 = (128 + 1024 + 128 * 36 + 2 * 32 * 72) * 4;
    constexpr int FSM   = (2 * 64 * 68 + 2 * 64 * 136) * 4;
    constexpr int RSM64 = (64 * 68 + 64 * 72) * 4;
    constexpr int RSM32 = (64 * 36 + 32 * 72) * 4;
    cudaFuncSetAttribute(k_conv_mma<64>, cudaFuncAttributeMaxDynamicSharedMemorySize, CSM64);
    cudaFuncSetAttribute(k_conv_mma<32>, cudaFuncAttributeMaxDynamicSharedMemorySize, CSM32);
    cudaFuncSetAttribute(k_fc_mma<64, true>, cudaFuncAttributeMaxDynamicSharedMemorySize, FSM);
    cudaFuncSetAttribute(k_fc_mma<256, false>, cudaFuncAttributeMaxDynamicSharedMemorySize, FSM);
    cudaFuncSetAttribute(k_root<64>, cudaFuncAttributeMaxDynamicSharedMemorySize, RSM64);
    cudaFuncSetAttribute(k_root<32>, cudaFuncAttributeMaxDynamicSharedMemorySize, RSM32);

    k_init<<<ng, 256>>>(N);
    k_prep<<<eg, 256>>>(ei, pseudo, E);
    k_scan<<<1, 1024>>>(N, E);
    k_scatter<<<eg, 256>>>(ei, E);

    // layer 1: 1 -> 32
    k_conv1<<<(E + 7) / 8, 256>>>(x, ei, w[0], E);
    k_reduce1<<<(N + 15) / 16, 256>>>(x, root[0], bias[0], hA, N);
    // layer 2: 32 -> 64
    k_conv_mma<32><<<nchunks, 256, CSM32>>>(hA, w[1]);
    k_root<32><<<nb64, 128, RSM32>>>(hA, root[1], bias[1], rtb, N);
    k_reduceL<<<(N + 7) / 8, 256>>>(rtb, hB, N);
    // layers 3-6: 64 -> 64
    k_conv_mma<64><<<nchunks, 256, CSM64>>>(hB, w[2]);
    k_root<64><<<nb64, 128, RSM64>>>(hB, root[2], bias[2], rtb, N);
    k_reduceL<<<(N + 7) / 8, 256>>>(rtb, hA, N);

    k_conv_mma<64><<<nchunks, 256, CSM64>>>(hA, w[3]);
    k_root<64><<<nb64, 128, RSM64>>>(hA, root[3], bias[3], rtb, N);
    k_reduceL<<<(N + 7) / 8, 256>>>(rtb, hB, N);

    k_conv_mma<64><<<nchunks, 256, CSM64>>>(hB, w[4]);
    k_root<64><<<nb64, 128, RSM64>>>(hB, root[4], bias[4], rtb, N);
    k_reduceL<<<(N + 7) / 8, 256>>>(rtb, hA, N);

    k_conv_mma<64><<<nchunks, 256, CSM64>>>(hA, w[5]);
    k_root<64><<<nb64, 128, RSM64>>>(hA, root[5], bias[5], rtb, N);
    k_reduceL<<<(N + 7) / 8, 256>>>(rtb, hB, N);

    // fc1: [N,64] @ [64,256] + ELU
    k_fc_mma<64, true><<<dim3(nb64, 2), 256, FSM>>>(hB, fc1w, fc1b, h256, N, 256);
    // fc2: [N,256] @ [256,1024]
    k_fc_mma<256, false><<<dim3(nb64, 8), 256, FSM>>>(h256, fc2w, fc2b, out, N, 1024);
    // log_softmax in place
    k_lsm<<<N, 256>>>(out);
}

// round 9
// speedup vs baseline: 3.7653x; 1.2441x over previous
#include <cuda_runtime.h>
#include <cuda_fp16.h>
#include <math.h>
#include <stdint.h>

#define NMAX 10000
#define EMAX 160000
#define NCHUNKMAX 4608

// ---------------- weight-half buffer segment offsets (halves) ----------------
#define OFF_W2   0                       // 125*32*64 = 256000
#define OFF_W3   256000                  // 125*64*64 = 512000 each
#define OFF_W4   768000
#define OFF_W5   1280000
#define OFF_W6   1792000
#define OFF_R2   2304000                 // 32*64 = 2048
#define OFF_R3   2306048                 // 64*64 = 4096 each
#define OFF_R4   2310144
#define OFF_R5   2314240
#define OFF_R6   2318336
#define OFF_FC1  2322432                 // 256*64 = 16384
#define OFF_FC2  2338816                 // 1024*256 = 262144
#define WH_TOTAL 2600960

// ---------------- scratch (static device globals; no allocation) ----------------
__device__ __half g_hAh[NMAX * 64];
__device__ __half g_hBh[NMAX * 64];
__device__ __half g_h256h[NMAX * 256];
__device__ float  g_root[NMAX * 64];         // per-layer x@root + bias (fp32)
__device__ __half g_msgh[EMAX * 64];         // per-edge messages (fp16), dst-sorted slots
__device__ __half g_wh[WH_TOTAL];            // all weights, half, transposed [n][k]
__device__ float  g_basisE[EMAX * 8];
__device__ int    g_cellE[EMAX];
__device__ int    g_rankC[EMAX];
__device__ int    g_rankD[EMAX];
__device__ int    g_slotE[EMAX];
__device__ int    g_srcC[EMAX];
__device__ int    g_slotC[EMAX];
__device__ float  g_basisC[EMAX * 8];
__device__ int    g_cellCnt[64];
__device__ int    g_cellStart[65];
__device__ int    g_deg[NMAX];
__device__ int    g_dstStart[NMAX + 1];
__device__ int    g_chunkCell[NCHUNKMAX];
__device__ int    g_chunkBeg[NCHUNKMAX];
__device__ int    g_numChunks;

// ---------------- helpers ----------------
__device__ __forceinline__ uint32_t smem_u32(const void* p) {
    uint32_t a;
    asm("{ .reg .u64 t; cvta.to.shared.u64 t, %1; cvt.u32.u64 %0, t; }" : "=r"(a) : "l"(p));
    return a;
}
__device__ __forceinline__ void cp16(uint32_t sdst, const void* gsrc) {
    asm volatile("cp.async.cg.shared.global [%0], [%1], 16;" :: "r"(sdst), "l"(gsrc));
}
__device__ __forceinline__ void cp16z(uint32_t sdst, const void* gsrc, int sz) {
    asm volatile("cp.async.cg.shared.global [%0], [%1], 16, %2;" :: "r"(sdst), "l"(gsrc), "r"(sz));
}
#define CP_COMMIT() asm volatile("cp.async.commit_group;" ::: "memory")
template <int n> __device__ __forceinline__ void cp_wait() {
    asm volatile("cp.async.wait_group %0;" :: "n"(n) : "memory");
}

// m16n8k16 f16 mma.sync, fp32 accumulate (sm_80+)
__device__ __forceinline__ void mma16816(float* d, uint32_t a0, uint32_t a1, uint32_t a2, uint32_t a3,
                                         uint32_t b0, uint32_t b1) {
    asm volatile(
        "mma.sync.aligned.m16n8k16.row.col.f32.f16.f16.f32 "
        "{%0,%1,%2,%3}, {%4,%5,%6,%7}, {%8,%9}, {%0,%1,%2,%3};"
        : "+f"(d[0]), "+f"(d[1]), "+f"(d[2]), "+f"(d[3])
        : "r"(a0), "r"(a1), "r"(a2), "r"(a3), "r"(b0), "r"(b1));
}
__device__ __forceinline__ uint32_t hscale(uint32_t a, uint32_t s) {
    __half2 r = __hmul2(*reinterpret_cast<__half2*>(&a), *reinterpret_cast<__half2*>(&s));
    return *reinterpret_cast<uint32_t*>(&r);
}
__device__ __forceinline__ uint32_t hbcast(float s) {
    __half2 h = __half2half2(__float2half_rn(s));
    return *reinterpret_cast<uint32_t*>(&h);
}
__device__ __forceinline__ float elu_f(float v) {
    return v > 0.0f ? v : (__expf(v) - 1.0f);
}

// ---------------- init ----------------
__global__ void k_init(int N) {
    int i = blockIdx.x * blockDim.x + threadIdx.x;
    if (i < 64) g_cellCnt[i] = 0;
    if (i < N)  g_deg[i] = 0;
}

// ---------------- weight convert: all fp32 weights -> half, transposed [n][k] ----------------
__device__ __forceinline__ void w2h_seg(const float* src, __half* dst, int K, int NC, int KB,
                                        int i0, int i1, int tid, int stride) {
    int len = KB * K * NC;
    for (int i = tid + i0; i < i1; i += stride) {
        int li = i - i0;
        int kb = li / (K * NC);
        int rem = li % (K * NC);
        int n = rem / K, k = rem % K;
        dst[li] = __float2half(src[(size_t)kb * K * NC + (size_t)k * NC + n]);
    }
    (void)len;
}
__global__ void __launch_bounds__(256) k_wall(
    const float* w2, const float* w3, const float* w4, const float* w5, const float* w6,
    const float* r2, const float* r3, const float* r4, const float* r5, const float* r6,
    const float* fc1w, const float* fc2w) {
    int tid = blockIdx.x * 256 + threadIdx.x;
    int stride = gridDim.x * 256;
    w2h_seg(w2,  g_wh + OFF_W2, 32, 64, 125, OFF_W2, OFF_W3, tid, stride);
    w2h_seg(w3,  g_wh + OFF_W3, 64, 64, 125, OFF_W3, OFF_W4, tid, stride);
    w2h_seg(w4,  g_wh + OFF_W4, 64, 64, 125, OFF_W4, OFF_W5, tid, stride);
    w2h_seg(w5,  g_wh + OFF_W5, 64, 64, 125, OFF_W5, OFF_W6, tid, stride);
    w2h_seg(w6,  g_wh + OFF_W6, 64, 64, 125, OFF_W6, OFF_R2, tid, stride);
    w2h_seg(r2,  g_wh + OFF_R2, 32, 64, 1, OFF_R2, OFF_R3, tid, stride);
    w2h_seg(r3,  g_wh + OFF_R3, 64, 64, 1, OFF_R3, OFF_R4, tid, stride);
    w2h_seg(r4,  g_wh + OFF_R4, 64, 64, 1, OFF_R4, OFF_R5, tid, stride);
    w2h_seg(r5,  g_wh + OFF_R5, 64, 64, 1, OFF_R5, OFF_R6, tid, stride);
    w2h_seg(r6,  g_wh + OFF_R6, 64, 64, 1, OFF_R6, OFF_FC1, tid, stride);
    w2h_seg(fc1w, g_wh + OFF_FC1, 64, 256, 1, OFF_FC1, OFF_FC2, tid, stride);
    w2h_seg(fc2w, g_wh + OFF_FC2, 256, 1024, 1, OFF_FC2, WH_TOTAL, tid, stride);
}

// ---------------- per-edge: basis, cell, ranks ----------------
__global__ void k_prep(const int* __restrict__ ei, const float* __restrict__ ps, int E) {
    int e = blockIdx.x * blockDim.x + threadIdx.x;
    if (e >= E) return;
    int dst = ei[E + e];
    float fr[3];
    int lo[3];
#pragma unroll
    for (int d = 0; d < 3; d++) {
        float pos = ps[e * 3 + d] * 4.0f;
        float l = floorf(pos);
        l = fminf(fmaxf(l, 0.0f), 3.0f);
        lo[d] = (int)l;
        fr[d] = pos - l;
    }
    int cell = lo[0] * 16 + lo[1] * 4 + lo[2];
    g_cellE[e] = cell;
#pragma unroll
    for (int b = 0; b < 8; b++) {
        float w = 1.0f;
#pragma unroll
        for (int d = 0; d < 3; d++) w *= ((b >> d) & 1) ? fr[d] : (1.0f - fr[d]);
        g_basisE[e * 8 + b] = w;
    }
    g_rankC[e] = atomicAdd(&g_cellCnt[cell], 1);
    g_rankD[e] = atomicAdd(&g_deg[dst], 1);
}

// ---------------- scan: cell offsets, chunk list, degree prefix ----------------
__global__ void __launch_bounds__(1024) k_scan(int N, int E) {
    __shared__ int chOff[64];
    __shared__ int warpSums[32];
    int tid = threadIdx.x;
    if (tid == 0) {
        int s = 0;
        for (int c = 0; c < 64; c++) { g_cellStart[c] = s; s += g_cellCnt[c]; }
        g_cellStart[64] = s;
        int t = 0;
        for (int c = 0; c < 64; c++) { chOff[c] = t; t += (g_cellCnt[c] + 127) / 128; }
        g_numChunks = t;
    }
    __syncthreads();
    if (tid < 64) {
        int t = chOff[tid];
        for (int b = g_cellStart[tid]; b < g_cellStart[tid + 1]; b += 128) {
            g_chunkCell[t] = tid; g_chunkBeg[t] = b; t++;
        }
    }
    int per = (N + 1023) / 1024;
    int base = tid * per;
    int lv[16];
    int s = 0;
#pragma unroll 16
    for (int i = 0; i < 16; i++) {
        if (i >= per) break;
        int v = (base + i < N) ? g_deg[base + i] : 0;
        lv[i] = s; s += v;
    }
    int lane = tid & 31, warp = tid >> 5;
    int incl = s;
#pragma unroll
    for (int off = 1; off < 32; off <<= 1) {
        int t2 = __shfl_up_sync(0xFFFFFFFF, incl, off);
        if (lane >= off) incl += t2;
    }
    if (lane == 31) warpSums[warp] = incl;
    __syncthreads();
    if (warp == 0) {
        int w = (lane < 32) ? warpSums[lane] : 0;
        int wi = w;
#pragma unroll
        for (int off = 1; off < 32; off <<= 1) {
            int t2 = __shfl_up_sync(0xFFFFFFFF, wi, off);
            if (lane >= off) wi += t2;
        }
        warpSums[lane] = wi - w;
    }
    __syncthreads();
    int off0 = warpSums[warp] + (incl - s);
#pragma unroll 16
    for (int i = 0; i < 16; i++) {
        if (i >= per) break;
        if (base + i < N) g_dstStart[base + i] = off0 + lv[i];
    }
    if (tid == 1023) g_dstStart[N] = off0;
}

// ---------------- scatter ----------------
__global__ void k_scatter(const int* __restrict__ ei, int E) {
    int e = blockIdx.x * blockDim.x + threadIdx.x;
    if (e >= E) return;
    int src = ei[e], dst = ei[E + e];
    int p = g_cellStart[g_cellE[e]] + g_rankC[e];
    int q = g_dstStart[dst] + g_rankD[e];
    g_srcC[p] = src;
    g_slotC[p] = q;
    g_slotE[e] = q;
#pragma unroll
    for (int b = 0; b < 8; b++) g_basisC[p * 8 + b] = g_basisE[e * 8 + b];
}

// ---------------- f16 mma spline-conv: 128-edge chunk x CO=64 ----------------
// 8 warps 4(m) x 2(n); warp tile 32x32; 2 m-atoms x 4 n-atoms of m16n8k16.
// A = basis-scaled X (half, scale via HMUL2); B = Wh[corner] [n][k] half.
template <int CI>
__global__ void __launch_bounds__(256) k_conv_h(const __half* __restrict__ xin,
                                                const __half* __restrict__ Wh) {
    constexpr int XPH = (CI == 64) ? 72 : 40;   // half stride; /2 mod 32 in {4,20} -> conflict-free
    constexpr int KP  = XPH;
    constexpr int XROWCH = CI / 16;             // 16B chunks per thread (2 thr/row)
    constexpr int WCH = 8 * CI;                 // 16B chunks per W tile (64 rows x CI/8)
    extern __shared__ char smc[];
    int*    slots = (int*)smc;                              // 128 ints
    float*  bsm   = (float*)(smc + 512);                    // 128 x 8
    __half* Xs    = (__half*)(smc + 512 + 4096);            // 128 x XPH
    __half* Ws    = Xs + 128 * XPH;                         // 2 x 64 x KP

    int bi = blockIdx.x;
    if (bi >= g_numChunks) return;
    int cell = g_chunkCell[bi];
    int beg  = g_chunkBeg[bi];
    int R = min(beg + 128, g_cellStart[cell + 1]) - beg;

    int tid = threadIdx.x, wid = tid >> 5, lid = tid & 31;
    int ix = cell >> 4, iy = (cell >> 2) & 3, iz = cell & 3;
    int kbs[8];
#pragma unroll
    for (int b = 0; b < 8; b++)
        kbs[b] = (ix + (b & 1)) * 25 + (iy + ((b >> 1) & 1)) * 5 + (iz + ((b >> 2) & 1));

    uint32_t sXs = smem_u32(Xs), sWs = smem_u32(Ws);

    {   // stage X rows (half), 2 threads per row
        int r = tid >> 1, half = tid & 1;
        bool valid = r < R;
        if (half == 0) {
            slots[r] = valid ? g_slotC[beg + r] : -1;
#pragma unroll
            for (int b = 0; b < 8; b++)
                bsm[r * 8 + b] = valid ? g_basisC[(beg + r) * 8 + b] : 0.0f;
        }
        int src = valid ? g_srcC[beg + r] : 0;
        const __half* xp = xin + (size_t)src * CI + half * (CI / 2);
        int sz = valid ? 16 : 0;
#pragma unroll
        for (int i = 0; i < XROWCH; i++)
            cp16z(sXs + (r * XPH + half * (CI / 2) + i * 8) * 2, xp + i * 8, sz);
    }
    {   // W prefetch corners 0,1
        const __half* wp = Wh + (size_t)kbs[0] * 64 * CI;
        for (int i = tid; i < WCH; i += 256) {
            int row = i / (CI / 8), c8 = i % (CI / 8);
            cp16(sWs + (row * KP + c8 * 8) * 2, wp + row * CI + c8 * 8);
        }
        CP_COMMIT();
        const __half* wp1 = Wh + (size_t)kbs[1] * 64 * CI;
        for (int i = tid; i < WCH; i += 256) {
            int row = i / (CI / 8), c8 = i % (CI / 8);
            cp16(sWs + (64 * KP + row * KP + c8 * 8) * 2, wp1 + row * CI + c8 * 8);
        }
        CP_COMMIT();
    }

    int wm = wid >> 1, wn = wid & 1;
    int g = lid >> 2, q = lid & 3;
    float acc[2][4][4];
#pragma unroll
    for (int m = 0; m < 2; m++)
#pragma unroll
        for (int n = 0; n < 4; n++)
#pragma unroll
            for (int i = 0; i < 4; i++) acc[m][n][i] = 0.0f;

#pragma unroll
    for (int b = 0; b < 8; b++) {
        if (b < 7) cp_wait<1>(); else cp_wait<0>();
        __syncthreads();

        const __half* Wb = Ws + (b & 1) * 64 * KP;
        uint32_t hs0[2], hs1[2];
#pragma unroll
        for (int m = 0; m < 2; m++) {
            int rr = wm * 32 + m * 16 + g;
            hs0[m] = hbcast(bsm[rr * 8 + b]);
            hs1[m] = hbcast(bsm[(rr + 8) * 8 + b]);
        }
#pragma unroll
        for (int ks = 0; ks < CI / 16; ks++) {
            int k0 = ks * 16;
            uint32_t B0[4], B1[4];
#pragma unroll
            for (int n = 0; n < 4; n++) {
                int c = wn * 32 + n * 8 + g;
                B0[n] = *(const uint32_t*)&Wb[c * KP + k0 + 2 * q];
                B1[n] = *(const uint32_t*)&Wb[c * KP + k0 + 2 * q + 8];
            }
#pragma unroll
            for (int m = 0; m < 2; m++) {
                int rr = wm * 32 + m * 16 + g;
                uint32_t a0 = hscale(*(const uint32_t*)&Xs[rr * XPH + k0 + 2 * q], hs0[m]);
                uint32_t a1 = hscale(*(const uint32_t*)&Xs[(rr + 8) * XPH + k0 + 2 * q], hs1[m]);
                uint32_t a2 = hscale(*(const uint32_t*)&Xs[rr * XPH + k0 + 2 * q + 8], hs0[m]);
                uint32_t a3 = hscale(*(const uint32_t*)&Xs[(rr + 8) * XPH + k0 + 2 * q + 8], hs1[m]);
#pragma unroll
                for (int n = 0; n < 4; n++)
                    mma16816(acc[m][n], a0, a1, a2, a3, B0[n], B1[n]);
            }
        }
        __syncthreads();
        if (b + 2 < 8) {
            const __half* wp = Wh + (size_t)kbs[b + 2] * 64 * CI;
            uint32_t dstb = sWs + ((b & 1) * 64 * KP) * 2;
            for (int i = tid; i < WCH; i += 256) {
                int row = i / (CI / 8), c8 = i % (CI / 8);
                cp16(dstb + (row * KP + c8 * 8) * 2, wp + row * CI + c8 * 8);
            }
            CP_COMMIT();
        }
    }

    // store messages fp16
#pragma unroll
    for (int m = 0; m < 2; m++)
#pragma unroll
        for (int h = 0; h < 2; h++) {
            int row = wm * 32 + m * 16 + g + h * 8;
            int slot = slots[row];
            if (slot >= 0) {
                __half2* base = (__half2*)(g_msgh + (size_t)slot * 64 + wn * 32);
#pragma unroll
                for (int n = 0; n < 4; n++)
                    base[(n * 8 + q * 2) >> 1] =
                        __floats2half2_rn(acc[m][n][h * 2], acc[m][n][h * 2 + 1]);
            }
        }
}

// ---------------- layer 1 (CI=1, CO=32) ----------------
__global__ void k_conv1(const float* __restrict__ x, const int* __restrict__ ei,
                        const float* __restrict__ w1, int E) {
    int e = blockIdx.x * 8 + (threadIdx.x >> 5);
    if (e >= E) return;
    int c = threadIdx.x & 31;
    int cell = g_cellE[e];
    int ix = cell >> 4, iy = (cell >> 2) & 3, iz = cell & 3;
    float acc = 0.0f;
#pragma unroll
    for (int b = 0; b < 8; b++) {
        int kb = (ix + (b & 1)) * 25 + (iy + ((b >> 1) & 1)) * 5 + (iz + ((b >> 2) & 1));
        acc += g_basisE[e * 8 + b] * w1[kb * 32 + c];
    }
    g_msgh[(size_t)g_slotE[e] * 32 + c] = __float2half(x[ei[e]] * acc);
}

// ---------------- root GEMM (f16): g_root = X @ root + bias, NC=64 ----------------
template <int CI>
__global__ void __launch_bounds__(128) k_root(const __half* __restrict__ X,
                                              const __half* __restrict__ rootw,
                                              const float* __restrict__ bias,
                                              float* __restrict__ out, int M) {
    constexpr int XPH = (CI == 64) ? 72 : 40;
    constexpr int KP  = XPH;
    extern __shared__ char smc[];
    __half* As = (__half*)smc;              // 64 x XPH
    __half* Bs = As + 64 * XPH;             // 64 x KP
    uint32_t sAs = smem_u32(As), sBs = smem_u32(Bs);
    int rb = blockIdx.x * 64;
    int tid = threadIdx.x, wid = tid >> 5, lid = tid & 31;
    int wm = wid >> 1, wn = wid & 1;
    int g = lid >> 2, q = lid & 3;

    constexpr int ACH = 8 * CI;             // 64 rows x CI/8 chunks
    for (int i = tid; i < ACH; i += 128) {
        int row = i / (CI / 8), c8 = i % (CI / 8);
        int gr = rb + row;
        cp16z(sAs + (row * XPH + c8 * 8) * 2,
              X + (size_t)min(gr, M - 1) * CI + c8 * 8, (gr < M) ? 16 : 0);
    }
    for (int i = tid; i < ACH; i += 128) {
        int row = i / (CI / 8), c8 = i % (CI / 8);
        cp16(sBs + (row * KP + c8 * 8) * 2, rootw + row * CI + c8 * 8);
    }
    CP_COMMIT();
    cp_wait<0>();
    __syncthreads();

    float acc[2][4][4];
#pragma unroll
    for (int m = 0; m < 2; m++)
#pragma unroll
        for (int n = 0; n < 4; n++)
#pragma unroll
            for (int i = 0; i < 4; i++) acc[m][n][i] = 0.0f;

#pragma unroll
    for (int ks = 0; ks < CI / 16; ks++) {
        int k0 = ks * 16;
        uint32_t B0[4], B1[4];
#pragma unroll
        for (int n = 0; n < 4; n++) {
            int c = wn * 32 + n * 8 + g;
            B0[n] = *(const uint32_t*)&Bs[c * KP + k0 + 2 * q];
            B1[n] = *(const uint32_t*)&Bs[c * KP + k0 + 2 * q + 8];
        }
#pragma unroll
        for (int m = 0; m < 2; m++) {
            int rr = wm * 32 + m * 16 + g;
            uint32_t a0 = *(const uint32_t*)&As[rr * XPH + k0 + 2 * q];
            uint32_t a1 = *(const uint32_t*)&As[(rr + 8) * XPH + k0 + 2 * q];
            uint32_t a2 = *(const uint32_t*)&As[rr * XPH + k0 + 2 * q + 8];
            uint32_t a3 = *(const uint32_t*)&As[(rr + 8) * XPH + k0 + 2 * q + 8];
#pragma unroll
            for (int n = 0; n < 4; n++)
                mma16816(acc[m][n], a0, a1, a2, a3, B0[n], B1[n]);
        }
    }

#pragma unroll
    for (int m = 0; m < 2; m++)
#pragma unroll
        for (int h = 0; h < 2; h++) {
            int gr = rb + wm * 32 + m * 16 + g + h * 8;
            if (gr >= M) continue;
#pragma unroll
            for (int n = 0; n < 4; n++) {
                int col = wn * 32 + n * 8 + q * 2;
                float2 bv = *(const float2*)&bias[col];
                *(float2*)&out[(size_t)gr * 64 + col] =
                    make_float2(acc[m][n][h * 2] + bv.x, acc[m][n][h * 2 + 1] + bv.y);
            }
        }
}

// ---------------- light reduce (CO=64): mean(msg) + rootbuf, ELU, half out ----------------
__global__ void __launch_bounds__(256) k_reduceL(const float* __restrict__ rootb,
                                                 __half* __restrict__ xout, int N) {
    int n = blockIdx.x * 8 + (threadIdx.x >> 5);
    if (n >= N) return;
    int jp = threadIdx.x & 31;
    int s0 = g_dstStart[n], s1 = g_dstStart[n + 1];
    float sx = 0.0f, sy = 0.0f;
    for (int r = s0; r < s1; r++) {
        float2 v = __half22float2(((const __half2*)(g_msgh + (size_t)r * 64))[jp]);
        sx += v.x; sy += v.y;
    }
    float inv = 1.0f / (float)max(g_deg[n], 1);
    float2 rb = *(const float2*)&rootb[(size_t)n * 64 + jp * 2];
    ((__half2*)(xout + (size_t)n * 64))[jp] =
        __floats2half2_rn(elu_f(sx * inv + rb.x), elu_f(sy * inv + rb.y));
}

// ---------------- layer-1 reduce (CO=32), root inline, half out ----------------
__global__ void __launch_bounds__(256) k_reduce1(const float* __restrict__ x,
                                                 const float* __restrict__ root1,
                                                 const float* __restrict__ b1,
                                                 __half* __restrict__ xout, int N) {
    int n = blockIdx.x * 16 + (threadIdx.x >> 4);
    if (n >= N) return;
    int jp = threadIdx.x & 15;
    int s0 = g_dstStart[n], s1 = g_dstStart[n + 1];
    float sx = 0.0f, sy = 0.0f;
    for (int r = s0; r < s1; r++) {
        float2 v = __half22float2(((const __half2*)(g_msgh + (size_t)r * 32))[jp]);
        sx += v.x; sy += v.y;
    }
    float inv = 1.0f / (float)max(g_deg[n], 1);
    float xn = x[n];
    float2 rv = *(const float2*)&root1[jp * 2];
    float2 bv = *(const float2*)&b1[jp * 2];
    ((__half2*)(xout + (size_t)n * 32))[jp] =
        __floats2half2_rn(elu_f(sx * inv + xn * rv.x + bv.x), elu_f(sy * inv + xn * rv.y + bv.y));
}

// ---------------- FC GEMM f16: block 64x128, warp 32x32, pipelined ----------------
// A [M][KD] half, Bh [NC][KD] half (transposed), bias fp32.
template <int KD, bool DOELU, bool OUTH>
__global__ void __launch_bounds__(256) k_fc_h(const __half* __restrict__ A,
                                              const __half* __restrict__ Bh,
                                              const float* __restrict__ bias,
                                              void* __restrict__ Cv, int M, int NC) {
    constexpr int APH = 72, BPH = 72;
    constexpr int NIT = KD / 64;
    extern __shared__ char smc[];
    __half* As = (__half*)smc;              // 2 x 64 x APH
    __half* Bs = As + 2 * 64 * APH;         // 2 x 128 x BPH
    uint32_t sAs = smem_u32(As), sBs = smem_u32(Bs);
    int rb = blockIdx.x * 64, cb = blockIdx.y * 128;
    int tid = threadIdx.x, wid = tid >> 5, lid = tid & 31;
    int wm = wid >> 2, wn = wid & 3;
    int g = lid >> 2, q = lid & 3;

    auto stage = [&](int it, int buf) {
        int kc = it * 64;
        for (int i = tid; i < 512; i += 256) {          // A: 64 rows x 8 chunks
            int row = i >> 3, c8 = i & 7;
            int gr = rb + row;
            cp16z(sAs + (buf * 64 * APH + row * APH + c8 * 8) * 2,
                  A + (size_t)min(gr, M - 1) * KD + kc + c8 * 8, (gr < M) ? 16 : 0);
        }
        for (int i = tid; i < 1024; i += 256) {         // B: 128 rows x 8 chunks
            int row = i >> 3, c8 = i & 7;
            cp16(sBs + (buf * 128 * BPH + row * BPH + c8 * 8) * 2,
                 Bh + (size_t)(cb + row) * KD + kc + c8 * 8);
        }
        CP_COMMIT();
    };

    float acc[2][4][4];
#pragma unroll
    for (int m = 0; m < 2; m++)
#pragma unroll
        for (int n = 0; n < 4; n++)
#pragma unroll
            for (int i = 0; i < 4; i++) acc[m][n][i] = 0.0f;

    stage(0, 0);
    if (NIT > 1) stage(1, 1);

#pragma unroll
    for (int it = 0; it < NIT; it++) {
        if (it + 1 < NIT) cp_wait<1>(); else cp_wait<0>();
        __syncthreads();
        const __half* Ab = As + (it & 1) * 64 * APH;
        const __half* Bb = Bs + (it & 1) * 128 * BPH;
#pragma unroll
        for (int ks = 0; ks < 4; ks++) {
            int k0 = ks * 16;
            uint32_t B0[4], B1[4];
#pragma unroll
            for (int n = 0; n < 4; n++) {
                int c = wn * 32 + n * 8 + g;
                B0[n] = *(const uint32_t*)&Bb[c * BPH + k0 + 2 * q];
                B1[n] = *(const uint32_t*)&Bb[c * BPH + k0 + 2 * q + 8];
            }
#pragma unroll
            for (int m = 0; m < 2; m++) {
                int rr = wm * 32 + m * 16 + g;
                uint32_t a0 = *(const uint32_t*)&Ab[rr * APH + k0 + 2 * q];
                uint32_t a1 = *(const uint32_t*)&Ab[(rr + 8) * APH + k0 + 2 * q];
                uint32_t a2 = *(const uint32_t*)&Ab[rr * APH + k0 + 2 * q + 8];
                uint32_t a3 = *(const uint32_t*)&Ab[(rr + 8) * APH + k0 + 2 * q + 8];
#pragma unroll
                for (int n = 0; n < 4; n++)
                    mma16816(acc[m][n], a0, a1, a2, a3, B0[n], B1[n]);
            }
        }
        __syncthreads();
        if (it + 2 < NIT) stage(it + 2, it & 1);
    }

#pragma unroll
    for (int m = 0; m < 2; m++)
#pragma unroll
        for (int h = 0; h < 2; h++) {
            int gr = rb + wm * 32 + m * 16 + g + h * 8;
            if (gr >= M) continue;
#pragma unroll
            for (int n = 0; n < 4; n++) {
                int col = cb + wn * 32 + n * 8 + q * 2;
                float v0 = acc[m][n][h * 2] + bias[col];
                float v1 = acc[m][n][h * 2 + 1] + bias[col + 1];
                if (DOELU) { v0 = elu_f(v0); v1 = elu_f(v1); }
                if (OUTH) {
                    *(__half2*)((__half*)Cv + (size_t)gr * NC + col) = __floats2half2_rn(v0, v1);
                } else {
                    *(float2*)((float*)Cv + (size_t)gr * NC + col) = make_float2(v0, v1);
                }
            }
        }
}

// ---------------- log_softmax ----------------
__global__ void k_lsm(float* __restrict__ out) {
    __shared__ float red[256];
    int n = blockIdx.x;
    float* row = out + (size_t)n * 1024;
    int tid = threadIdx.x;
    float v[4];
    float m = -INFINITY;
#pragma unroll
    for (int i = 0; i < 4; i++) { v[i] = row[tid + 256 * i]; m = fmaxf(m, v[i]); }
    red[tid] = m;
    __syncthreads();
    for (int off = 128; off; off >>= 1) {
        if (tid < off) red[tid] = fmaxf(red[tid], red[tid + off]);
        __syncthreads();
    }
    m = red[0];
    __syncthreads();
    float s = 0.0f;
#pragma unroll
    for (int i = 0; i < 4; i++) s += __expf(v[i] - m);
    red[tid] = s;
    __syncthreads();
    for (int off = 128; off; off >>= 1) {
        if (tid < off) red[tid] += red[tid + off];
        __syncthreads();
    }
    float l = m + __logf(red[0]);
#pragma unroll
    for (int i = 0; i < 4; i++) row[tid + 256 * i] = v[i] - l;
}

// ---------------- launcher ----------------
extern "C" void kernel_launch(void* const* d_in, const int* in_sizes, int n_in,
                              void* d_out, int out_size) {
    const float* x      = (const float*)d_in[0];
    const int*   ei     = (const int*)d_in[1];
    const float* pseudo = (const float*)d_in[2];
    const float *w[6], *root[6], *bias[6];
    for (int i = 0; i < 6; i++) {
        w[i]    = (const float*)d_in[3 + 3 * i];
        root[i] = (const float*)d_in[4 + 3 * i];
        bias[i] = (const float*)d_in[5 + 3 * i];
    }
    const float* fc1w = (const float*)d_in[21];
    const float* fc1b = (const float*)d_in[22];
    const float* fc2w = (const float*)d_in[23];
    const float* fc2b = (const float*)d_in[24];
    float* out = (float*)d_out;

    int N = in_sizes[0];
    int E = in_sizes[1] / 2;

    int eg = (E + 255) / 256;
    int ng = (N + 255) / 256;
    int nchunks = (E + 127) / 128 + 64;
    int nb64 = (N + 63) / 64;

    __half* hAh = nullptr;  cudaGetSymbolAddress((void**)&hAh, g_hAh);
    __half* hBh = nullptr;  cudaGetSymbolAddress((void**)&hBh, g_hBh);
    __half* h256h = nullptr; cudaGetSymbolAddress((void**)&h256h, g_h256h);
    float*  rtb = nullptr;  cudaGetSymbolAddress((void**)&rtb, g_root);
    __half* wh = nullptr;   cudaGetSymbolAddress((void**)&wh, g_wh);

    constexpr int CSM64 = 512 + 4096 + (128 * 72 + 2 * 64 * 72) * 2;   // 41472
    constexpr int CSM32 = 512 + 4096 + (128 * 40 + 2 * 64 * 40) * 2;   // 25088
    constexpr int FSM   = (2 * 64 * 72 + 2 * 128 * 72) * 2;            // 55296
    constexpr int RSM64 = (64 * 72 + 64 * 72) * 2;                     // 18432
    constexpr int RSM32 = (64 * 40 + 64 * 40) * 2;                     // 10240
    cudaFuncSetAttribute(k_conv_h<64>, cudaFuncAttributeMaxDynamicSharedMemorySize, CSM64);
    cudaFuncSetAttribute(k_conv_h<32>, cudaFuncAttributeMaxDynamicSharedMemorySize, CSM32);
    cudaFuncSetAttribute((const void*)k_fc_h<64, true, true>, cudaFuncAttributeMaxDynamicSharedMemorySize, FSM);
    cudaFuncSetAttribute((const void*)k_fc_h<256, false, false>, cudaFuncAttributeMaxDynamicSharedMemorySize, FSM);
    cudaFuncSetAttribute(k_root<64>, cudaFuncAttributeMaxDynamicSharedMemorySize, RSM64);
    cudaFuncSetAttribute(k_root<32>, cudaFuncAttributeMaxDynamicSharedMemorySize, RSM32);

    k_init<<<ng, 256>>>(N);
    k_prep<<<eg, 256>>>(ei, pseudo, E);
    k_scan<<<1, 1024>>>(N, E);
    k_scatter<<<eg, 256>>>(ei, E);
    k_wall<<<160, 256>>>(w[1], w[2], w[3], w[4], w[5],
                         root[1], root[2], root[3], root[4], root[5], fc1w, fc2w);

    // layer 1: 1 -> 32
    k_conv1<<<(E + 7) / 8, 256>>>(x, ei, w[0], E);
    k_reduce1<<<(N + 15) / 16, 256>>>(x, root[0], bias[0], hAh, N);
    // layer 2: 32 -> 64
    k_conv_h<32><<<nchunks, 256, CSM32>>>(hAh, wh + OFF_W2);
    k_root<32><<<nb64, 128, RSM32>>>(hAh, wh + OFF_R2, bias[1], rtb, N);
    k_reduceL<<<(N + 7) / 8, 256>>>(rtb, hBh, N);
    // layers 3-6: 64 -> 64
    k_conv_h<64><<<nchunks, 256, CSM64>>>(hBh, wh + OFF_W3);
    k_root<64><<<nb64, 128, RSM64>>>(hBh, wh + OFF_R3, bias[2], rtb, N);
    k_reduceL<<<(N + 7) / 8, 256>>>(rtb, hAh, N);

    k_conv_h<64><<<nchunks, 256, CSM64>>>(hAh, wh + OFF_W4);
    k_root<64><<<nb64, 128, RSM64>>>(hAh, wh + OFF_R4, bias[3], rtb, N);
    k_reduceL<<<(N + 7) / 8, 256>>>(rtb, hBh, N);

    k_conv_h<64><<<nchunks, 256, CSM64>>>(hBh, wh + OFF_W5);
    k_root<64><<<nb64, 128, RSM64>>>(hBh, wh + OFF_R5, bias[4], rtb, N);
    k_reduceL<<<(N + 7) / 8, 256>>>(rtb, hAh, N);

    k_conv_h<64><<<nchunks, 256, CSM64>>>(hAh, wh + OFF_W6);
    k_root<64><<<nb64, 128, RSM64>>>(hAh, wh + OFF_R6, bias[5], rtb, N);
    k_reduceL<<<(N + 7) / 8, 256>>>(rtb, hBh, N);

    // fc1: [N,64] @ [64,256] + ELU -> half
    k_fc_h<64, true, true><<<dim3(nb64, 2), 256, FSM>>>(hBh, wh + OFF_FC1, fc1b, h256h, N, 256);
    // fc2: [N,256] @ [256,1024] -> fp32 logits
    k_fc_h<256, false, false><<<dim3(nb64, 8), 256, FSM>>>(h256h, wh + OFF_FC2, fc2b, out, N, 1024);
    // log_softmax in place
    k_lsm<<<N, 256>>>(out);
}

// round 11
// speedup vs baseline: 4.1274x; 1.0962x over previous
#include <cuda_runtime.h>
#include <cuda_fp16.h>
#include <math.h>
#include <stdint.h>

#define NMAX 10000
#define EMAX 160000
#define NCHUNKMAX 4608

// ---------------- weight-half buffer segment offsets (halves) ----------------
#define OFF_W2   0                       // 125*32*64
#define OFF_W3   256000                  // 125*64*64 each
#define OFF_W4   768000
#define OFF_W5   1280000
#define OFF_W6   1792000
#define OFF_R2   2304000                 // 32*64
#define OFF_R3   2306048                 // 64*64 each
#define OFF_R4   2310144
#define OFF_R5   2314240
#define OFF_R6   2318336
#define OFF_FC1  2322432                 // 256*64
#define OFF_FC2  2338816                 // 1024*256
#define WH_TOTAL 2600960

// ---------------- scratch (static device globals; no allocation) ----------------
__device__ __half g_hAh[NMAX * 64];
__device__ __half g_hBh[NMAX * 64];
__device__ __half g_h256h[NMAX * 256];
__device__ float  g_root[NMAX * 64];
__device__ __half g_msgh[EMAX * 64];
__device__ __half g_wh[WH_TOTAL];
__device__ int    g_cellE[EMAX];
__device__ int    g_rankC[EMAX];
__device__ int    g_rankD[EMAX];
__device__ int    g_slotE[EMAX];
__device__ int    g_srcC[EMAX];
__device__ int    g_slotC[EMAX];
__device__ float  g_basisC[EMAX * 8];
__device__ int    g_cellCnt[64];
__device__ int    g_cellStart[65];
__device__ int    g_deg[NMAX];
__device__ int    g_dstStart[NMAX + 1];
__device__ int    g_chunkCell[NCHUNKMAX];
__device__ int    g_chunkBeg[NCHUNKMAX];
__device__ int    g_numChunks;

// ---------------- helpers ----------------
__device__ __forceinline__ uint32_t smem_u32(const void* p) {
    uint32_t a;
    asm("{ .reg .u64 t; cvta.to.shared.u64 t, %1; cvt.u32.u64 %0, t; }" : "=r"(a) : "l"(p));
    return a;
}
__device__ __forceinline__ void cp16(uint32_t sdst, const void* gsrc) {
    asm volatile("cp.async.cg.shared.global [%0], [%1], 16;" :: "r"(sdst), "l"(gsrc));
}
__device__ __forceinline__ void cp16z(uint32_t sdst, const void* gsrc, int sz) {
    asm volatile("cp.async.cg.shared.global [%0], [%1], 16, %2;" :: "r"(sdst), "l"(gsrc), "r"(sz));
}
#define CP_COMMIT() asm volatile("cp.async.commit_group;" ::: "memory")
template <int n> __device__ __forceinline__ void cp_wait() {
    asm volatile("cp.async.wait_group %0;" :: "n"(n) : "memory");
}

__device__ __forceinline__ void mma16816(float* d, uint32_t a0, uint32_t a1, uint32_t a2, uint32_t a3,
                                         uint32_t b0, uint32_t b1) {
    asm volatile(
        "mma.sync.aligned.m16n8k16.row.col.f32.f16.f16.f32 "
        "{%0,%1,%2,%3}, {%4,%5,%6,%7}, {%8,%9}, {%0,%1,%2,%3};"
        : "+f"(d[0]), "+f"(d[1]), "+f"(d[2]), "+f"(d[3])
        : "r"(a0), "r"(a1), "r"(a2), "r"(a3), "r"(b0), "r"(b1));
}
__device__ __forceinline__ uint32_t hscale(uint32_t a, uint32_t s) {
    __half2 r = __hmul2(*reinterpret_cast<__half2*>(&a), *reinterpret_cast<__half2*>(&s));
    return *reinterpret_cast<uint32_t*>(&r);
}
__device__ __forceinline__ uint32_t hbcast(float s) {
    __half2 h = __half2half2(__float2half_rn(s));
    return *reinterpret_cast<uint32_t*>(&h);
}
__device__ __forceinline__ float elu_f(float v) {
    return v > 0.0f ? v : (__expf(v) - 1.0f);
}
// basis weights from pseudo, recomputed wherever needed
__device__ __forceinline__ void basis_of(const float* __restrict__ ps, int e,
                                         float* fr, int* cell) {
#pragma unroll
    for (int d = 0; d < 3; d++) {
        float pos = ps[e * 3 + d] * 4.0f;
        float l = floorf(pos);
        l = fminf(fmaxf(l, 0.0f), 3.0f);
        fr[d] = pos - l;
        if (d == 0) *cell = (int)l * 16;
        else if (d == 1) *cell += (int)l * 4;
        else *cell += (int)l;
    }
}
__device__ __forceinline__ float basis_w(const float* fr, int b) {
    float w = 1.0f;
#pragma unroll
    for (int d = 0; d < 3; d++) w *= ((b >> d) & 1) ? fr[d] : (1.0f - fr[d]);
    return w;
}

// ---------------- init ----------------
__global__ void k_init(int N) {
    int i = blockIdx.x * blockDim.x + threadIdx.x;
    if (i < 64) g_cellCnt[i] = 0;
    if (i < N)  g_deg[i] = 0;
}

// ---------------- prep (edges) + weight convert (extra blocks) ----------------
__device__ __forceinline__ void w2h_seg(const float* src, __half* dst, int K, int NC, int KB,
                                        int i0, int i1, int tid, int stride) {
    for (int i = tid + i0; i < i1; i += stride) {
        int li = i - i0;
        int kb = li / (K * NC);
        int rem = li % (K * NC);
        int n = rem / K, k = rem % K;
        dst[li] = __float2half(src[(size_t)kb * K * NC + (size_t)k * NC + n]);
    }
}
__global__ void __launch_bounds__(256) k_prep(
    const int* __restrict__ ei, const float* __restrict__ ps, int E, int eg,
    const float* w2, const float* w3, const float* w4, const float* w5, const float* w6,
    const float* r2, const float* r3, const float* r4, const float* r5, const float* r6,
    const float* fc1w, const float* fc2w) {
    int b = blockIdx.x;
    if (b < eg) {
        int e = b * 256 + threadIdx.x;
        if (e >= E) return;
        float fr[3];
        int cell;
        basis_of(ps, e, fr, &cell);
        g_cellE[e] = cell;
        g_rankC[e] = atomicAdd(&g_cellCnt[cell], 1);
        g_rankD[e] = atomicAdd(&g_deg[ei[E + e]], 1);
    } else {
        int tid = (b - eg) * 256 + threadIdx.x;
        int stride = (gridDim.x - eg) * 256;
        w2h_seg(w2,  g_wh + OFF_W2, 32, 64, 125, OFF_W2, OFF_W3, tid, stride);
        w2h_seg(w3,  g_wh + OFF_W3, 64, 64, 125, OFF_W3, OFF_W4, tid, stride);
        w2h_seg(w4,  g_wh + OFF_W4, 64, 64, 125, OFF_W4, OFF_W5, tid, stride);
        w2h_seg(w5,  g_wh + OFF_W5, 64, 64, 125, OFF_W5, OFF_W6, tid, stride);
        w2h_seg(w6,  g_wh + OFF_W6, 64, 64, 125, OFF_W6, OFF_R2, tid, stride);
        w2h_seg(r2,  g_wh + OFF_R2, 32, 64, 1, OFF_R2, OFF_R3, tid, stride);
        w2h_seg(r3,  g_wh + OFF_R3, 64, 64, 1, OFF_R3, OFF_R4, tid, stride);
        w2h_seg(r4,  g_wh + OFF_R4, 64, 64, 1, OFF_R4, OFF_R5, tid, stride);
        w2h_seg(r5,  g_wh + OFF_R5, 64, 64, 1, OFF_R5, OFF_R6, tid, stride);
        w2h_seg(r6,  g_wh + OFF_R6, 64, 64, 1, OFF_R6, OFF_FC1, tid, stride);
        w2h_seg(fc1w, g_wh + OFF_FC1, 64, 256, 1, OFF_FC1, OFF_FC2, tid, stride);
        w2h_seg(fc2w, g_wh + OFF_FC2, 256, 1024, 1, OFF_FC2, WH_TOTAL, tid, stride);
    }
}

// ---------------- scan: cell offsets, chunk list, degree prefix ----------------
__global__ void __launch_bounds__(1024) k_scan(int N, int E) {
    __shared__ int chOff[64];
    __shared__ int warpSums[32];
    int tid = threadIdx.x;
    if (tid == 0) {
        int s = 0;
        for (int c = 0; c < 64; c++) { g_cellStart[c] = s; s += g_cellCnt[c]; }
        g_cellStart[64] = s;
        int t = 0;
        for (int c = 0; c < 64; c++) { chOff[c] = t; t += (g_cellCnt[c] + 127) / 128; }
        g_numChunks = t;
    }
    __syncthreads();
    if (tid < 64) {
        int t = chOff[tid];
        for (int b = g_cellStart[tid]; b < g_cellStart[tid + 1]; b += 128) {
            g_chunkCell[t] = tid; g_chunkBeg[t] = b; t++;
        }
    }
    int per = (N + 1023) / 1024;
    int base = tid * per;
    int lv[16];
    int s = 0;
#pragma unroll 16
    for (int i = 0; i < 16; i++) {
        if (i >= per) break;
        int v = (base + i < N) ? g_deg[base + i] : 0;
        lv[i] = s; s += v;
    }
    int lane = tid & 31, warp = tid >> 5;
    int incl = s;
#pragma unroll
    for (int off = 1; off < 32; off <<= 1) {
        int t2 = __shfl_up_sync(0xFFFFFFFF, incl, off);
        if (lane >= off) incl += t2;
    }
    if (lane == 31) warpSums[warp] = incl;
    __syncthreads();
    if (warp == 0) {
        int w = (lane < 32) ? warpSums[lane] : 0;
        int wi = w;
#pragma unroll
        for (int off = 1; off < 32; off <<= 1) {
            int t2 = __shfl_up_sync(0xFFFFFFFF, wi, off);
            if (lane >= off) wi += t2;
        }
        warpSums[lane] = wi - w;
    }
    __syncthreads();
    int off0 = warpSums[warp] + (incl - s);
#pragma unroll 16
    for (int i = 0; i < 16; i++) {
        if (i >= per) break;
        if (base + i < N) g_dstStart[base + i] = off0 + lv[i];
    }
    if (tid == 1023) g_dstStart[N] = off0;
}

// ---------------- scatter: basis recomputed from pseudo ----------------
__global__ void k_scatter(const int* __restrict__ ei, const float* __restrict__ ps, int E) {
    int e = blockIdx.x * blockDim.x + threadIdx.x;
    if (e >= E) return;
    int src = ei[e], dst = ei[E + e];
    float fr[3];
    int cell;
    basis_of(ps, e, fr, &cell);
    int p = g_cellStart[cell] + g_rankC[e];
    int q = g_dstStart[dst] + g_rankD[e];
    g_srcC[p] = src;
    g_slotC[p] = q;
    g_slotE[e] = q;
#pragma unroll
    for (int b = 0; b < 8; b++) g_basisC[p * 8 + b] = basis_w(fr, b);
}

// ---------------- fused conv (f16 mma) + root GEMM (tail blocks) ----------------
template <int CI>
__global__ void __launch_bounds__(256) k_convroot(const __half* __restrict__ xin,
                                                  const __half* __restrict__ Wh,
                                                  const __half* __restrict__ rootw,
                                                  const float* __restrict__ bias,
                                                  float* __restrict__ rootout,
                                                  int M, int nbRoot) {
    constexpr int XPH = (CI == 64) ? 72 : 40;
    constexpr int KP  = XPH;
    constexpr int XROWCH = CI / 16;
    constexpr int WCH = 8 * CI;
    extern __shared__ char smc[];

    int bi = blockIdx.x;
    int nch = g_numChunks;
    int tid = threadIdx.x, wid = tid >> 5, lid = tid & 31;
    int g = lid >> 2, q = lid & 3;

    if (bi >= nch) {
        // ---------- root path: out[64 rows] = X @ rootw + bias ----------
        int rbIdx = bi - nch;
        if (rbIdx >= nbRoot) return;
        __half* As = (__half*)smc;              // 64 x XPH
        __half* Bs = As + 64 * XPH;             // 64 x KP
        uint32_t sAs = smem_u32(As), sBs = smem_u32(Bs);
        int rb = rbIdx * 64;
        constexpr int ACH = 8 * CI;
        for (int i = tid; i < ACH; i += 256) {
            int row = i / (CI / 8), c8 = i % (CI / 8);
            int gr = rb + row;
            cp16z(sAs + (row * XPH + c8 * 8) * 2,
                  xin + (size_t)min(gr, M - 1) * CI + c8 * 8, (gr < M) ? 16 : 0);
        }
        for (int i = tid; i < ACH; i += 256) {
            int row = i / (CI / 8), c8 = i % (CI / 8);
            cp16(sBs + (row * KP + c8 * 8) * 2, rootw + row * CI + c8 * 8);
        }
        CP_COMMIT();
        cp_wait<0>();
        __syncthreads();
        if (wid < 4) {
            int wm = wid >> 1, wn = wid & 1;
            float acc[2][4][4];
#pragma unroll
            for (int m = 0; m < 2; m++)
#pragma unroll
                for (int n = 0; n < 4; n++)
#pragma unroll
                    for (int i = 0; i < 4; i++) acc[m][n][i] = 0.0f;
#pragma unroll
            for (int ks = 0; ks < CI / 16; ks++) {
                int k0 = ks * 16;
                uint32_t B0[4], B1[4];
#pragma unroll
                for (int n = 0; n < 4; n++) {
                    int c = wn * 32 + n * 8 + g;
                    B0[n] = *(const uint32_t*)&Bs[c * KP + k0 + 2 * q];
                    B1[n] = *(const uint32_t*)&Bs[c * KP + k0 + 2 * q + 8];
                }
#pragma unroll
                for (int m = 0; m < 2; m++) {
                    int rr = wm * 32 + m * 16 + g;
                    uint32_t a0 = *(const uint32_t*)&As[rr * XPH + k0 + 2 * q];
                    uint32_t a1 = *(const uint32_t*)&As[(rr + 8) * XPH + k0 + 2 * q];
                    uint32_t a2 = *(const uint32_t*)&As[rr * XPH + k0 + 2 * q + 8];
                    uint32_t a3 = *(const uint32_t*)&As[(rr + 8) * XPH + k0 + 2 * q + 8];
#pragma unroll
                    for (int n = 0; n < 4; n++)
                        mma16816(acc[m][n], a0, a1, a2, a3, B0[n], B1[n]);
                }
            }
#pragma unroll
            for (int m = 0; m < 2; m++)
#pragma unroll
                for (int h = 0; h < 2; h++) {
                    int gr = rb + wm * 32 + m * 16 + g + h * 8;
                    if (gr >= M) continue;
#pragma unroll
                    for (int n = 0; n < 4; n++) {
                        int col = wn * 32 + n * 8 + q * 2;
                        float2 bv = *(const float2*)&bias[col];
                        *(float2*)&rootout[(size_t)gr * 64 + col] =
                            make_float2(acc[m][n][h * 2] + bv.x, acc[m][n][h * 2 + 1] + bv.y);
                    }
                }
        }
        return;
    }

    // ---------- conv path ----------
    int*    slots = (int*)smc;
    float*  bsm   = (float*)(smc + 512);
    __half* Xs    = (__half*)(smc + 512 + 4096);
    __half* Ws    = Xs + 128 * XPH;

    int cell = g_chunkCell[bi];
    int beg  = g_chunkBeg[bi];
    int R = min(beg + 128, g_cellStart[cell + 1]) - beg;

    int ix = cell >> 4, iy = (cell >> 2) & 3, iz = cell & 3;
    int kbs[8];
#pragma unroll
    for (int b = 0; b < 8; b++)
        kbs[b] = (ix + (b & 1)) * 25 + (iy + ((b >> 1) & 1)) * 5 + (iz + ((b >> 2) & 1));

    uint32_t sXs = smem_u32(Xs), sWs = smem_u32(Ws);

    {
        int r = tid >> 1, half = tid & 1;
        bool valid = r < R;
        if (half == 0) {
            slots[r] = valid ? g_slotC[beg + r] : -1;
#pragma unroll
            for (int b = 0; b < 8; b++)
                bsm[r * 8 + b] = valid ? g_basisC[(beg + r) * 8 + b] : 0.0f;
        }
        int src = valid ? g_srcC[beg + r] : 0;
        const __half* xp = xin + (size_t)src * CI + half * (CI / 2);
        int sz = valid ? 16 : 0;
#pragma unroll
        for (int i = 0; i < XROWCH; i++)
            cp16z(sXs + (r * XPH + half * (CI / 2) + i * 8) * 2, xp + i * 8, sz);
    }
    {
        const __half* wp = Wh + (size_t)kbs[0] * 64 * CI;
        for (int i = tid; i < WCH; i += 256) {
            int row = i / (CI / 8), c8 = i % (CI / 8);
            cp16(sWs + (row * KP + c8 * 8) * 2, wp + row * CI + c8 * 8);
        }
        CP_COMMIT();
        const __half* wp1 = Wh + (size_t)kbs[1] * 64 * CI;
        for (int i = tid; i < WCH; i += 256) {
            int row = i / (CI / 8), c8 = i % (CI / 8);
            cp16(sWs + (64 * KP + row * KP + c8 * 8) * 2, wp1 + row * CI + c8 * 8);
        }
        CP_COMMIT();
    }

    int wm = wid >> 1, wn = wid & 1;
    float acc[2][4][4];
#pragma unroll
    for (int m = 0; m < 2; m++)
#pragma unroll
        for (int n = 0; n < 4; n++)
#pragma unroll
            for (int i = 0; i < 4; i++) acc[m][n][i] = 0.0f;

#pragma unroll
    for (int b = 0; b < 8; b++) {
        if (b < 7) cp_wait<1>(); else cp_wait<0>();
        __syncthreads();

        const __half* Wb = Ws + (b & 1) * 64 * KP;
        uint32_t hs0[2], hs1[2];
#pragma unroll
        for (int m = 0; m < 2; m++) {
            int rr = wm * 32 + m * 16 + g;
            hs0[m] = hbcast(bsm[rr * 8 + b]);
            hs1[m] = hbcast(bsm[(rr + 8) * 8 + b]);
        }
#pragma unroll
        for (int ks = 0; ks < CI / 16; ks++) {
            int k0 = ks * 16;
            uint32_t B0[4], B1[4];
#pragma unroll
            for (int n = 0; n < 4; n++) {
                int c = wn * 32 + n * 8 + g;
                B0[n] = *(const uint32_t*)&Wb[c * KP + k0 + 2 * q];
                B1[n] = *(const uint32_t*)&Wb[c * KP + k0 + 2 * q + 8];
            }
#pragma unroll
            for (int m = 0; m < 2; m++) {
                int rr = wm * 32 + m * 16 + g;
                uint32_t a0 = hscale(*(const uint32_t*)&Xs[rr * XPH + k0 + 2 * q], hs0[m]);
                uint32_t a1 = hscale(*(const uint32_t*)&Xs[(rr + 8) * XPH + k0 + 2 * q], hs1[m]);
                uint32_t a2 = hscale(*(const uint32_t*)&Xs[rr * XPH + k0 + 2 * q + 8], hs0[m]);
                uint32_t a3 = hscale(*(const uint32_t*)&Xs[(rr + 8) * XPH + k0 + 2 * q + 8], hs1[m]);
#pragma unroll
                for (int n = 0; n < 4; n++)
                    mma16816(acc[m][n], a0, a1, a2, a3, B0[n], B1[n]);
            }
        }
        __syncthreads();
        if (b + 2 < 8) {
            const __half* wp = Wh + (size_t)kbs[b + 2] * 64 * CI;
            uint32_t dstb = sWs + ((b & 1) * 64 * KP) * 2;
            for (int i = tid; i < WCH; i += 256) {
                int row = i / (CI / 8), c8 = i % (CI / 8);
                cp16(dstb + (row * KP + c8 * 8) * 2, wp + row * CI + c8 * 8);
            }
            CP_COMMIT();
        }
    }

#pragma unroll
    for (int m = 0; m < 2; m++)
#pragma unroll
        for (int h = 0; h < 2; h++) {
            int row = wm * 32 + m * 16 + g + h * 8;
            int slot = slots[row];
            if (slot >= 0) {
                __half2* base = (__half2*)(g_msgh + (size_t)slot * 64 + wn * 32);
#pragma unroll
                for (int n = 0; n < 4; n++)
                    base[(n * 8 + q * 2) >> 1] =
                        __floats2half2_rn(acc[m][n][h * 2], acc[m][n][h * 2 + 1]);
            }
        }
}

// ---------------- layer 1 (CI=1, CO=32): basis recomputed ----------------
__global__ void k_conv1(const float* __restrict__ x, const int* __restrict__ ei,
                        const float* __restrict__ ps, const float* __restrict__ w1, int E) {
    int e = blockIdx.x * 8 + (threadIdx.x >> 5);
    if (e >= E) return;
    int c = threadIdx.x & 31;
    float fr[3];
    int cell;
    basis_of(ps, e, fr, &cell);
    int ix = cell >> 4, iy = (cell >> 2) & 3, iz = cell & 3;
    float acc = 0.0f;
#pragma unroll
    for (int b = 0; b < 8; b++) {
        int kb = (ix + (b & 1)) * 25 + (iy + ((b >> 1) & 1)) * 5 + (iz + ((b >> 2) & 1));
        acc += basis_w(fr, b) * w1[kb * 32 + c];
    }
    g_msgh[(size_t)g_slotE[e] * 32 + c] = __float2half(x[ei[e]] * acc);
}

// ---------------- light reduce (CO=64): mean(msg) + rootbuf, ELU, half out ----------------
__global__ void __launch_bounds__(256) k_reduceL(const float* __restrict__ rootb,
                                                 __half* __restrict__ xout, int N) {
    int n = blockIdx.x * 8 + (threadIdx.x >> 5);
    if (n >= N) return;
    int jp = threadIdx.x & 31;
    int s0 = g_dstStart[n], s1 = g_dstStart[n + 1];
    float sx = 0.0f, sy = 0.0f, sx2 = 0.0f, sy2 = 0.0f;
    int r = s0;
    for (; r + 2 <= s1; r += 2) {
        float2 v0 = __half22float2(((const __half2*)(g_msgh + (size_t)r * 64))[jp]);
        float2 v1 = __half22float2(((const __half2*)(g_msgh + (size_t)(r + 1) * 64))[jp]);
        sx += v0.x; sy += v0.y;
        sx2 += v1.x; sy2 += v1.y;
    }
    if (r < s1) {
        float2 v = __half22float2(((const __half2*)(g_msgh + (size_t)r * 64))[jp]);
        sx += v.x; sy += v.y;
    }
    sx += sx2; sy += sy2;
    float inv = 1.0f / (float)max(g_deg[n], 1);
    float2 rb = *(const float2*)&rootb[(size_t)n * 64 + jp * 2];
    ((__half2*)(xout + (size_t)n * 64))[jp] =
        __floats2half2_rn(elu_f(sx * inv + rb.x), elu_f(sy * inv + rb.y));
}

// ---------------- layer-1 reduce (CO=32), root inline, half out ----------------
__global__ void __launch_bounds__(256) k_reduce1(const float* __restrict__ x,
                                                 const float* __restrict__ root1,
                                                 const float* __restrict__ b1,
                                                 __half* __restrict__ xout, int N) {
    int n = blockIdx.x * 16 + (threadIdx.x >> 4);
    if (n >= N) return;
    int jp = threadIdx.x & 15;
    int s0 = g_dstStart[n], s1 = g_dstStart[n + 1];
    float sx = 0.0f, sy = 0.0f;
    for (int r = s0; r < s1; r++) {
        float2 v = __half22float2(((const __half2*)(g_msgh + (size_t)r * 32))[jp]);
        sx += v.x; sy += v.y;
    }
    float inv = 1.0f / (float)max(g_deg[n], 1);
    float xn = x[n];
    float2 rv = *(const float2*)&root1[jp * 2];
    float2 bv = *(const float2*)&b1[jp * 2];
    ((__half2*)(xout + (size_t)n * 32))[jp] =
        __floats2half2_rn(elu_f(sx * inv + xn * rv.x + bv.x), elu_f(sy * inv + xn * rv.y + bv.y));
}

// ---------------- FC GEMM f16: block 64x128, warp 32x32, pipelined ----------------
template <int KD, bool DOELU, bool OUTH>
__global__ void __launch_bounds__(256) k_fc_h(const __half* __restrict__ A,
                                              const __half* __restrict__ Bh,
                                              const float* __restrict__ bias,
                                              void* __restrict__ Cv, int M, int NC) {
    constexpr int APH = 72, BPH = 72;
    constexpr int NIT = KD / 64;
    extern __shared__ char smc[];
    __half* As = (__half*)smc;
    __half* Bs = As + 2 * 64 * APH;
    uint32_t sAs = smem_u32(As), sBs = smem_u32(Bs);
    int rb = blockIdx.x * 64, cb = blockIdx.y * 128;
    int tid = threadIdx.x, wid = tid >> 5, lid = tid & 31;
    int wm = wid >> 2, wn = wid & 3;
    int g = lid >> 2, q = lid & 3;

    auto stage = [&](int it, int buf) {
        int kc = it * 64;
        for (int i = tid; i < 512; i += 256) {
            int row = i >> 3, c8 = i & 7;
            int gr = rb + row;
            cp16z(sAs + (buf * 64 * APH + row * APH + c8 * 8) * 2,
                  A + (size_t)min(gr, M - 1) * KD + kc + c8 * 8, (gr < M) ? 16 : 0);
        }
        for (int i = tid; i < 1024; i += 256) {
            int row = i >> 3, c8 = i & 7;
            cp16(sBs + (buf * 128 * BPH + row * BPH + c8 * 8) * 2,
                 Bh + (size_t)(cb + row) * KD + kc + c8 * 8);
        }
        CP_COMMIT();
    };

    float acc[2][4][4];
#pragma unroll
    for (int m = 0; m < 2; m++)
#pragma unroll
        for (int n = 0; n < 4; n++)
#pragma unroll
            for (int i = 0; i < 4; i++) acc[m][n][i] = 0.0f;

    stage(0, 0);
    if (NIT > 1) stage(1, 1);

#pragma unroll
    for (int it = 0; it < NIT; it++) {
        if (it + 1 < NIT) cp_wait<1>(); else cp_wait<0>();
        __syncthreads();
        const __half* Ab = As + (it & 1) * 64 * APH;
        const __half* Bb = Bs + (it & 1) * 128 * BPH;
#pragma unroll
        for (int ks = 0; ks < 4; ks++) {
            int k0 = ks * 16;
            uint32_t B0[4], B1[4];
#pragma unroll
            for (int n = 0; n < 4; n++) {
                int c = wn * 32 + n * 8 + g;
                B0[n] = *(const uint32_t*)&Bb[c * BPH + k0 + 2 * q];
                B1[n] = *(const uint32_t*)&Bb[c * BPH + k0 + 2 * q + 8];
            }
#pragma unroll
            for (int m = 0; m < 2; m++) {
                int rr = wm * 32 + m * 16 + g;
                uint32_t a0 = *(const uint32_t*)&Ab[rr * APH + k0 + 2 * q];
                uint32_t a1 = *(const uint32_t*)&Ab[(rr + 8) * APH + k0 + 2 * q];
                uint32_t a2 = *(const uint32_t*)&Ab[rr * APH + k0 + 2 * q + 8];
                uint32_t a3 = *(const uint32_t*)&Ab[(rr + 8) * APH + k0 + 2 * q + 8];
#pragma unroll
                for (int n = 0; n < 4; n++)
                    mma16816(acc[m][n], a0, a1, a2, a3, B0[n], B1[n]);
            }
        }
        __syncthreads();
        if (it + 2 < NIT) stage(it + 2, it & 1);
    }

#pragma unroll
    for (int m = 0; m < 2; m++)
#pragma unroll
        for (int h = 0; h < 2; h++) {
            int gr = rb + wm * 32 + m * 16 + g + h * 8;
            if (gr >= M) continue;
#pragma unroll
            for (int n = 0; n < 4; n++) {
                int col = cb + wn * 32 + n * 8 + q * 2;
                float v0 = acc[m][n][h * 2] + bias[col];
                float v1 = acc[m][n][h * 2 + 1] + bias[col + 1];
                if (DOELU) { v0 = elu_f(v0); v1 = elu_f(v1); }
                if (OUTH) {
                    *(__half2*)((__half*)Cv + (size_t)gr * NC + col) = __floats2half2_rn(v0, v1);
                } else {
                    *(float2*)((float*)Cv + (size_t)gr * NC + col) = make_float2(v0, v1);
                }
            }
        }
}

// ---------------- log_softmax ----------------
__global__ void k_lsm(float* __restrict__ out) {
    __shared__ float red[256];
    int n = blockIdx.x;
    float* row = out + (size_t)n * 1024;
    int tid = threadIdx.x;
    float v[4];
    float m = -INFINITY;
#pragma unroll
    for (int i = 0; i < 4; i++) { v[i] = row[tid + 256 * i]; m = fmaxf(m, v[i]); }
    red[tid] = m;
    __syncthreads();
    for (int off = 128; off; off >>= 1) {
        if (tid < off) red[tid] = fmaxf(red[tid], red[tid + off]);
        __syncthreads();
    }
    m = red[0];
    __syncthreads();
    float s = 0.0f;
#pragma unroll
    for (int i = 0; i < 4; i++) s += __expf(v[i] - m);
    red[tid] = s;
    __syncthreads();
    for (int off = 128; off; off >>= 1) {
        if (tid < off) red[tid] += red[tid + off];
        __syncthreads();
    }
    float l = m + __logf(red[0]);
#pragma unroll
    for (int i = 0; i < 4; i++) row[tid + 256 * i] = v[i] - l;
}

// ---------------- launcher ----------------
extern "C" void kernel_launch(void* const* d_in, const int* in_sizes, int n_in,
                              void* d_out, int out_size) {
    const float* x      = (const float*)d_in[0];
    const int*   ei     = (const int*)d_in[1];
    const float* pseudo = (const float*)d_in[2];
    const float *w[6], *root[6], *bias[6];
    for (int i = 0; i < 6; i++) {
        w[i]    = (const float*)d_in[3 + 3 * i];
        root[i] = (const float*)d_in[4 + 3 * i];
        bias[i] = (const float*)d_in[5 + 3 * i];
    }
    const float* fc1w = (const float*)d_in[21];
    const float* fc1b = (const float*)d_in[22];
    const float* fc2w = (const float*)d_in[23];
    const float* fc2b = (const float*)d_in[24];
    float* out = (float*)d_out;

    int N = in_sizes[0];
    int E = in_sizes[1] / 2;

    int eg = (E + 255) / 256;
    int ng = (N + 255) / 256;
    int nchunksUB = (E + 127) / 128 + 64;
    int nb64 = (N + 63) / 64;
    int cgrid = nchunksUB + nb64;           // conv chunks + root tail blocks

    __half* hAh = nullptr;  cudaGetSymbolAddress((void**)&hAh, g_hAh);
    __half* hBh = nullptr;  cudaGetSymbolAddress((void**)&hBh, g_hBh);
    __half* h256h = nullptr; cudaGetSymbolAddress((void**)&h256h, g_h256h);
    float*  rtb = nullptr;  cudaGetSymbolAddress((void**)&rtb, g_root);
    __half* wh = nullptr;   cudaGetSymbolAddress((void**)&wh, g_wh);

    constexpr int CSM64 = 512 + 4096 + (128 * 72 + 2 * 64 * 72) * 2;   // 41472
    constexpr int CSM32 = 512 + 4096 + (128 * 40 + 2 * 64 * 40) * 2;   // 25088
    constexpr int FSM   = (2 * 64 * 72 + 2 * 128 * 72) * 2;            // 55296
    cudaFuncSetAttribute(k_convroot<64>, cudaFuncAttributeMaxDynamicSharedMemorySize, CSM64);
    cudaFuncSetAttribute(k_convroot<32>, cudaFuncAttributeMaxDynamicSharedMemorySize, CSM32);
    cudaFuncSetAttribute((const void*)k_fc_h<64, true, true>, cudaFuncAttributeMaxDynamicSharedMemorySize, FSM);
    cudaFuncSetAttribute((const void*)k_fc_h<256, false, false>, cudaFuncAttributeMaxDynamicSharedMemorySize, FSM);

    k_init<<<ng, 256>>>(N);
    k_prep<<<eg + 160, 256>>>(ei, pseudo, E, eg,
                              w[1], w[2], w[3], w[4], w[5],
                              root[1], root[2], root[3], root[4], root[5], fc1w, fc2w);
    k_scan<<<1, 1024>>>(N, E);
    k_scatter<<<eg, 256>>>(ei, pseudo, E);

    // layer 1: 1 -> 32
    k_conv1<<<(E + 7) / 8, 256>>>(x, ei, pseudo, w[0], E);
    k_reduce1<<<(N + 15) / 16, 256>>>(x, root[0], bias[0], hAh, N);
    // layer 2: 32 -> 64 (conv + root fused in one launch)
    k_convroot<32><<<cgrid, 256, CSM32>>>(hAh, wh + OFF_W2, wh + OFF_R2, bias[1], rtb, N, nb64);
    k_reduceL<<<(N + 7) / 8, 256>>>(rtb, hBh, N);
    // layers 3-6: 64 -> 64
    k_convroot<64><<<cgrid, 256, CSM64>>>(hBh, wh + OFF_W3, wh + OFF_R3, bias[2], rtb, N, nb64);
    k_reduceL<<<(N + 7) / 8, 256>>>(rtb, hAh, N);

    k_convroot<64><<<cgrid, 256, CSM64>>>(hAh, wh + OFF_W4, wh + OFF_R4, bias[3], rtb, N, nb64);
    k_reduceL<<<(N + 7) / 8, 256>>>(rtb, hBh, N);

    k_convroot<64><<<cgrid, 256, CSM64>>>(hBh, wh + OFF_W5, wh + OFF_R5, bias[4], rtb, N, nb64);
    k_reduceL<<<(N + 7) / 8, 256>>>(rtb, hAh, N);

    k_convroot<64><<<cgrid, 256, CSM64>>>(hAh, wh + OFF_W6, wh + OFF_R6, bias[5], rtb, N, nb64);
    k_reduceL<<<(N + 7) / 8, 256>>>(rtb, hBh, N);

    // fc1: [N,64] @ [64,256] + ELU -> half
    k_fc_h<64, true, true><<<dim3(nb64, 2), 256, FSM>>>(hBh, wh + OFF_FC1, fc1b, h256h, N, 256);
    // fc2: [N,256] @ [256,1024] -> fp32 logits
    k_fc_h<256, false, false><<<dim3(nb64, 8), 256, FSM>>>(h256h, wh + OFF_FC2, fc2b, out, N, 1024);
    // log_softmax in place
    k_lsm<<<N, 256>>>(out);
}